// round 5
// baseline (speedup 1.0000x reference)
#include <cuda_runtime.h>
#include <cstdint>

typedef unsigned long long u64;
typedef unsigned int u32;

// ---------------- packed fp32x2 helpers (attention kernel) ----------------
__device__ __forceinline__ u64 pack2(float x, float y) {
    u64 r; asm("mov.b64 %0, {%1, %2};" : "=l"(r) : "f"(x), "f"(y)); return r;
}
__device__ __forceinline__ float2 unpack2(u64 v) {
    float2 r; asm("mov.b64 {%0, %1}, %2;" : "=f"(r.x), "=f"(r.y) : "l"(v)); return r;
}
__device__ __forceinline__ void fma2(u64& d, u64 a, u64 b) {
    asm("fma.rn.f32x2 %0, %1, %2, %0;" : "+l"(d) : "l"(a), "l"(b));
}
__device__ __forceinline__ u64 mul2(u64 a, u64 b) {
    u64 d; asm("mul.rn.f32x2 %0, %1, %2;" : "=l"(d) : "l"(a), "l"(b)); return d;
}

// ---------------- tf32 helpers ----------------
__device__ __forceinline__ float tf32r(float x) {
    float r; asm("cvt.rna.tf32.f32 %0, %1;" : "=f"(r) : "f"(x)); return r;
}
// m16n8k8 tf32 MMA, row.col, fp32 accumulate (baseline PTX, sm_80+)
__device__ __forceinline__ void mma8(float* c, u32 a0, u32 a1, u32 a2, u32 a3,
                                     u32 b0, u32 b1) {
    asm volatile("mma.sync.aligned.m16n8k8.row.col.f32.tf32.tf32.f32 "
                 "{%0,%1,%2,%3}, {%4,%5,%6,%7}, {%8,%9}, {%0,%1,%2,%3};"
                 : "+f"(c[0]), "+f"(c[1]), "+f"(c[2]), "+f"(c[3])
                 : "r"(a0), "r"(a1), "r"(a2), "r"(a3), "r"(b0), "r"(b1));
}

// ---------------- scratch (device globals: allocation-free) ----------------
__device__ float g_Qt[4096 * 1024];
__device__ float g_Qd[4096 * 1024];
__device__ float g_Kt[1024 * 1024];
__device__ float g_Vt[1024 * 1024];
__device__ float g_Kd[1024 * 1024];
__device__ float g_Vd[1024 * 1024];
__device__ float g_Ct[4096 * 1024];
__device__ float g_Cd[4096 * 1024];
__device__ float g_H [4096 * 1024];
__device__ float g_gate[4096];

// ---------------- multi-operand GEMM argument block ----------------
struct GArg {
    const float* A[4];
    const float* A2[4];   // second K-segment source (DUAL only)
    const float* B[4];
    const float* bias[4];
    float*       C[4];
    const float* gate;
    int M, N, K, Ksplit;
};

// ---------------- HMMA 3xTF32 GEMM, 128x128 tile, k-stage 16 ----------------
// EPI 0: C = AB + bias
// EPI 1: C = relu(AB + bias)                  (with DUAL-A K concat)
// EPI 3: C = C + gate[r]*((AB + bias) - C)
//
// SMEM buffer layout (floats), per k8-chunk region = 128 entries * 10 (8B-aligned
// rows: 40 bytes — keeps every float2 frag load aligned):
//  Ah[2*1280] | Al[2*1280] | Bh[2*1280] | Bl[2*1280]   -> 10240 floats/buffer
//  A row entry:  row*10 + (k&3)*2 + (k>>2)   (pairs (k, k+4) contiguous)
//  B col entry:  col*10 + (k&3)*2 + (k>>2)
static constexpr int KCF   = 1280;          // floats per k-chunk region
static constexpr int BUF_F = 4 * 2 * KCF;   // 10240 floats
static constexpr int SMEM_DYN = 2 * BUF_F * 4;  // 81920 bytes

template<int EPI, bool DUAL>
__global__ __launch_bounds__(256, 2)
void tgemm(GArg g)
{
    extern __shared__ __align__(16) float smf[];

    const int tid  = threadIdx.x;
    const int wid  = tid >> 5;
    const int lane = tid & 31;
    const int gq   = lane >> 2;      // group id 0..7
    const int tq   = lane & 3;       // thread-in-group 0..3
    const int wr   = (wid & 1) * 64; // warp row offset in CTA tile
    const int wc   = (wid >> 1) * 32;// warp col offset

    const int z = blockIdx.z;
    const float* __restrict__ A    = g.A[z];
    const float* __restrict__ A2   = g.A2[z];
    const float* __restrict__ B    = g.B[z];
    const float* __restrict__ bias = g.bias[z];
    float* __restrict__ C          = g.C[z];
    const int M = g.M, N = g.N, K = g.K, Ksp = g.Ksplit;
    const int lda = DUAL ? Ksp : K;
    const int row0 = blockIdx.y * 128;
    const int col0 = blockIdx.x * 128;

    float acc[4][4][4];
    #pragma unroll
    for (int i = 0; i < 4; i++)
        #pragma unroll
        for (int j = 0; j < 4; j++)
            #pragma unroll
            for (int q = 0; q < 4; q++) acc[i][j][q] = 0.f;

    float4 aR[2], bR[2];

    auto ldg_stage = [&](int k0) {
        #pragma unroll
        for (int it = 0; it < 2; it++) {
            int slot = it * 256 + tid;
            int r = slot >> 2, c4 = slot & 3;
            int gr = row0 + r;
            int kk = k0 + c4 * 4;
            const float* base = A;
            if (DUAL && kk >= Ksp) { base = A2; kk -= Ksp; }
            aR[it] = (gr < M) ? *(const float4*)(base + (size_t)gr * lda + kk)
                              : make_float4(0.f, 0.f, 0.f, 0.f);
        }
        #pragma unroll
        for (int it = 0; it < 2; it++) {
            int slot = it * 256 + tid;
            int kr = slot >> 5, n4 = slot & 31;
            bR[it] = *(const float4*)(B + (size_t)(k0 + kr) * N + col0 + n4 * 4);
        }
    };
    auto sts_stage = [&](int buf) {
        float* fb = smf + buf * BUF_F;
        #pragma unroll
        for (int it = 0; it < 2; it++) {
            int slot = it * 256 + tid;
            int r = slot >> 2, c4 = slot & 3;
            int kc = c4 >> 1, e = c4 & 1;
            float v[4] = { aR[it].x, aR[it].y, aR[it].z, aR[it].w };
            #pragma unroll
            for (int j = 0; j < 4; j++) {
                float hi = tf32r(v[j]);
                float lo = tf32r(v[j] - hi);
                int off = kc * KCF + r * 10 + j * 2 + e;
                fb[off]           = hi;
                fb[2 * KCF + off] = lo;
            }
        }
        #pragma unroll
        for (int it = 0; it < 2; it++) {
            int slot = it * 256 + tid;
            int kr = slot >> 5, n4 = slot & 31;
            int kc = kr >> 3, kk = kr & 7;
            int s = kk & 3, e = kk >> 2;
            float v[4] = { bR[it].x, bR[it].y, bR[it].z, bR[it].w };
            #pragma unroll
            for (int j = 0; j < 4; j++) {
                float hi = tf32r(v[j]);
                float lo = tf32r(v[j] - hi);
                int off = kc * KCF + (n4 * 4 + j) * 10 + s * 2 + e;
                fb[4 * KCF + off] = hi;
                fb[6 * KCF + off] = lo;
            }
        }
    };

    auto ld_afrags = [&](const float* reg, u32 af[4][4]) {
        #pragma unroll
        for (int mi = 0; mi < 4; mi++) {
            int r = wr + mi * 16 + gq;
            float2 p0 = *(const float2*)(reg + r * 10 + tq * 2);
            float2 p1 = *(const float2*)(reg + (r + 8) * 10 + tq * 2);
            af[mi][0] = __float_as_uint(p0.x);  // a0: (gq,   k=tq)
            af[mi][2] = __float_as_uint(p0.y);  // a2: (gq,   k=tq+4)
            af[mi][1] = __float_as_uint(p1.x);  // a1: (gq+8, k=tq)
            af[mi][3] = __float_as_uint(p1.y);  // a3: (gq+8, k=tq+4)
        }
    };
    auto ld_bfrags = [&](const float* reg, u32 bf[4][2]) {
        #pragma unroll
        for (int ni = 0; ni < 4; ni++) {
            int c = wc + ni * 8 + gq;
            float2 p = *(const float2*)(reg + c * 10 + tq * 2);
            bf[ni][0] = __float_as_uint(p.x);   // b0: k=tq
            bf[ni][1] = __float_as_uint(p.y);   // b1: k=tq+4
        }
    };

    auto compute = [&](int buf) {
        const float* fb = smf + buf * BUF_F;
        #pragma unroll
        for (int kc = 0; kc < 2; kc++) {
            u32 af[4][4], bf[4][2], bf2[4][2];
            ld_afrags(fb + kc * KCF, af);                 // Ah
            ld_bfrags(fb + 4 * KCF + kc * KCF, bf);       // Bh
            #pragma unroll
            for (int mi = 0; mi < 4; mi++)
                #pragma unroll
                for (int ni = 0; ni < 4; ni++)
                    mma8(acc[mi][ni], af[mi][0], af[mi][1], af[mi][2], af[mi][3],
                         bf[ni][0], bf[ni][1]);
            ld_bfrags(fb + 6 * KCF + kc * KCF, bf2);      // Bl
            #pragma unroll
            for (int mi = 0; mi < 4; mi++)
                #pragma unroll
                for (int ni = 0; ni < 4; ni++)
                    mma8(acc[mi][ni], af[mi][0], af[mi][1], af[mi][2], af[mi][3],
                         bf2[ni][0], bf2[ni][1]);
            ld_afrags(fb + 2 * KCF + kc * KCF, af);       // Al
            #pragma unroll
            for (int mi = 0; mi < 4; mi++)
                #pragma unroll
                for (int ni = 0; ni < 4; ni++)
                    mma8(acc[mi][ni], af[mi][0], af[mi][1], af[mi][2], af[mi][3],
                         bf[ni][0], bf[ni][1]);
        }
    };

    // prologue
    ldg_stage(0);
    sts_stage(0);
    __syncthreads();

    const int nst = K / 16;
    for (int s = 0; s < nst; s++) {
        const int buf = s & 1;
        if (s + 1 < nst) ldg_stage((s + 1) * 16);
        compute(buf);
        if (s + 1 < nst) sts_stage(buf ^ 1);
        __syncthreads();
    }

    // epilogue: acc -> C
    #pragma unroll
    for (int mi = 0; mi < 4; mi++) {
        #pragma unroll
        for (int rr = 0; rr < 2; rr++) {
            int r = row0 + wr + mi * 16 + gq + rr * 8;
            if (r >= M) continue;
            float gg = (EPI == 3) ? g.gate[r] : 0.f;
            #pragma unroll
            for (int ni = 0; ni < 4; ni++) {
                int c = col0 + wc + ni * 8 + tq * 2;
                size_t idx = (size_t)r * N + c;
                float s0 = acc[mi][ni][rr * 2 + 0] + bias[c];
                float s1 = acc[mi][ni][rr * 2 + 1] + bias[c + 1];
                float2 o;
                if (EPI == 0) {
                    o = make_float2(s0, s1);
                } else if (EPI == 1) {
                    o = make_float2(fmaxf(s0, 0.f), fmaxf(s1, 0.f));
                } else {
                    float2 old = *(const float2*)(C + idx);
                    o = make_float2(old.x + gg * (s0 - old.x),
                                    old.y + gg * (s1 - old.y));
                }
                *(float2*)(C + idx) = o;
            }
        }
    }
}

// ---------------- flash attention: 1 thread per query row, online softmax ----
struct FArg {
    const float* Q[2];
    const float* Kb[2];
    const float* Vb[2];
    float*       O[2];
};

__global__ __launch_bounds__(64)
void flash_attn(FArg f, int S)
{
    __shared__ __align__(16) u64 Ks[64 * 32];
    __shared__ __align__(16) u64 Vs[64 * 32];
    __shared__ float Ss[64 * 64];
    const int tid = threadIdx.x;
    const int h   = blockIdx.y;
    const int sel = blockIdx.z >> 3;
    const int b   = blockIdx.z & 7;
    const int row = b * 512 + blockIdx.x * 64 + tid;

    const float* __restrict__ Q  = f.Q[sel];
    const float* __restrict__ Kb = f.Kb[sel];
    const float* __restrict__ Vb = f.Vb[sel];
    float* __restrict__ O        = f.O[sel];

    const u64* qp = (const u64*)(Q + (size_t)row * 1024 + h * 64);
    u64 q2[32];
    #pragma unroll
    for (int i = 0; i < 32; i++) q2[i] = qp[i];

    u64 acc2[32] = {};
    float m = -1e30f, lsum = 0.f;
    const float scale = 0.125f;

    for (int s0 = 0; s0 < S; s0 += 64) {
        int jmax = S - s0; if (jmax > 64) jmax = 64;
        #pragma unroll
        for (int i = 0; i < 32; i++) {
            int idx = i * 64 + tid;
            int j = idx >> 5, e2 = idx & 31;
            int srow = s0 + j;
            u64 kv = 0, vv = 0;
            if (srow < S) {
                kv = ((const u64*)(Kb + (size_t)srow * 1024 + h * 64))[e2];
                vv = ((const u64*)(Vb + (size_t)srow * 1024 + h * 64))[e2];
            }
            Ks[idx] = kv; Vs[idx] = vv;
        }
        __syncthreads();

        float tmax = -1e30f;
        for (int j = 0; j < 64; j++) {
            float s;
            if (j < jmax) {
                u64 s2 = 0;
                const ulonglong2* kp = (const ulonglong2*)&Ks[j * 32];
                #pragma unroll
                for (int e = 0; e < 16; e++) {
                    ulonglong2 kv = kp[e];
                    fma2(s2, q2[e * 2],     kv.x);
                    fma2(s2, q2[e * 2 + 1], kv.y);
                }
                float2 sf = unpack2(s2);
                s = (sf.x + sf.y) * scale;
            } else {
                s = -1e30f;
            }
            tmax = fmaxf(tmax, s);
            Ss[j * 64 + tid] = s;
        }

        float mnew  = fmaxf(m, tmax);
        float alpha = __expf(m - mnew);
        lsum *= alpha;
        u64 a2 = pack2(alpha, alpha);
        #pragma unroll
        for (int e = 0; e < 32; e++) acc2[e] = mul2(acc2[e], a2);

        for (int j = 0; j < 64; j++) {
            float p = __expf(Ss[j * 64 + tid] - mnew);
            lsum += p;
            u64 p2 = pack2(p, p);
            const ulonglong2* vp = (const ulonglong2*)&Vs[j * 32];
            #pragma unroll
            for (int e = 0; e < 16; e++) {
                ulonglong2 vv = vp[e];
                fma2(acc2[e * 2],     p2, vv.x);
                fma2(acc2[e * 2 + 1], p2, vv.y);
            }
        }
        m = mnew;
        __syncthreads();
    }

    float inv = 1.f / lsum;
    float2* op = (float2*)(O + (size_t)row * 1024 + h * 64);
    #pragma unroll
    for (int e = 0; e < 32; e++) {
        float2 v = unpack2(acc2[e]);
        v.x *= inv; v.y *= inv;
        op[e] = v;
    }
}

// ---------------- gate: G[r] = sigmoid(H[r,:] . W2 + b2), one warp per row ----
__global__ __launch_bounds__(256)
void gate_kernel(const float* __restrict__ H, const float* __restrict__ W2,
                 const float* __restrict__ b2, float* __restrict__ G)
{
    int w = (blockIdx.x * blockDim.x + threadIdx.x) >> 5;
    int lane = threadIdx.x & 31;
    const float* hp = H + (size_t)w * 1024;
    float s = 0.f;
    #pragma unroll
    for (int i = 0; i < 32; i++) s += hp[lane + i * 32] * W2[lane + i * 32];
    #pragma unroll
    for (int o = 16; o; o >>= 1) s += __shfl_xor_sync(0xffffffffu, s, o);
    if (lane == 0) G[w] = 1.f / (1.f + __expf(-(s + b2[0])));
}

// ---------------- launch ----------------
extern "C" void kernel_launch(void* const* d_in, const int* in_sizes, int n_in,
                              void* d_out, int out_size)
{
    const float* trend  = (const float*)d_in[0];
    const float* detail = (const float*)d_in[1];
    const float* protoT = (const float*)d_in[2];
    const float* protoD = (const float*)d_in[3];
    const float* tWq = (const float*)d_in[4];  const float* tbq = (const float*)d_in[5];
    const float* tWk = (const float*)d_in[6];  const float* tbk = (const float*)d_in[7];
    const float* tWv = (const float*)d_in[8];  const float* tbv = (const float*)d_in[9];
    const float* tWo = (const float*)d_in[10]; const float* tbo = (const float*)d_in[11];
    const float* dWq = (const float*)d_in[12]; const float* dbq = (const float*)d_in[13];
    const float* dWk = (const float*)d_in[14]; const float* dbk = (const float*)d_in[15];
    const float* dWv = (const float*)d_in[16]; const float* dbv = (const float*)d_in[17];
    const float* dWo = (const float*)d_in[18]; const float* dbo = (const float*)d_in[19];
    const float* gW1 = (const float*)d_in[20]; const float* gb1 = (const float*)d_in[21];
    const float* gW2 = (const float*)d_in[22]; const float* gb2 = (const float*)d_in[23];
    float* out = (float*)d_out;

    float *Qt, *Qd, *Kt, *Vt, *Kd, *Vd, *Ct, *Cd, *H, *G;
    cudaGetSymbolAddress((void**)&Qt, g_Qt);
    cudaGetSymbolAddress((void**)&Qd, g_Qd);
    cudaGetSymbolAddress((void**)&Kt, g_Kt);
    cudaGetSymbolAddress((void**)&Vt, g_Vt);
    cudaGetSymbolAddress((void**)&Kd, g_Kd);
    cudaGetSymbolAddress((void**)&Vd, g_Vd);
    cudaGetSymbolAddress((void**)&Ct, g_Ct);
    cudaGetSymbolAddress((void**)&Cd, g_Cd);
    cudaGetSymbolAddress((void**)&H,  g_H);
    cudaGetSymbolAddress((void**)&G,  g_gate);

    cudaFuncSetAttribute(tgemm<0, false>, cudaFuncAttributeMaxDynamicSharedMemorySize, SMEM_DYN);
    cudaFuncSetAttribute(tgemm<1, true >, cudaFuncAttributeMaxDynamicSharedMemorySize, SMEM_DYN);
    cudaFuncSetAttribute(tgemm<3, false>, cudaFuncAttributeMaxDynamicSharedMemorySize, SMEM_DYN);

    // 1) Q projections, merged (z=2)
    {
        GArg a = {};
        a.A[0] = trend;  a.B[0] = tWq; a.bias[0] = tbq; a.C[0] = Qt;
        a.A[1] = detail; a.B[1] = dWq; a.bias[1] = dbq; a.C[1] = Qd;
        a.M = 4096; a.N = 1024; a.K = 1024; a.Ksplit = 0;
        tgemm<0, false><<<dim3(8, 32, 2), 256, SMEM_DYN>>>(a);
    }
    // 2) K/V projections, merged (z=4)
    {
        GArg a = {};
        a.A[0] = protoT; a.B[0] = tWk; a.bias[0] = tbk; a.C[0] = Kt;
        a.A[1] = protoT; a.B[1] = tWv; a.bias[1] = tbv; a.C[1] = Vt;
        a.A[2] = protoD; a.B[2] = dWk; a.bias[2] = dbk; a.C[2] = Kd;
        a.A[3] = protoD; a.B[3] = dWv; a.bias[3] = dbv; a.C[3] = Vd;
        a.M = 1000; a.N = 1024; a.K = 4096; a.Ksplit = 0;
        tgemm<0, false><<<dim3(8, 8, 4), 256, SMEM_DYN>>>(a);
    }
    // 3) attention, both branches merged
    {
        FArg fa = {};
        fa.Q[0] = Qt; fa.Kb[0] = Kt; fa.Vb[0] = Vt; fa.O[0] = Ct;
        fa.Q[1] = Qd; fa.Kb[1] = Kd; fa.Vb[1] = Vd; fa.O[1] = Cd;
        flash_attn<<<dim3(8, 16, 16), 64>>>(fa, 1000);
    }
    // 4) gate MLP layer 1: H = relu([trend|detail] @ gW1 + gb1)
    {
        GArg a = {};
        a.A[0] = trend; a.A2[0] = detail; a.B[0] = gW1; a.bias[0] = gb1; a.C[0] = H;
        a.M = 4096; a.N = 1024; a.K = 2048; a.Ksplit = 1024;
        tgemm<1, true><<<dim3(8, 32, 1), 256, SMEM_DYN>>>(a);
    }
    // 5) gate
    gate_kernel<<<512, 256>>>(H, gW2, gb2, G);

    // 6) output projections + fused blend
    {
        GArg a = {};
        a.A[0] = Cd; a.B[0] = dWo; a.bias[0] = dbo; a.C[0] = out;
        a.M = 4096; a.N = 4096; a.K = 1024; a.Ksplit = 0;
        tgemm<0, false><<<dim3(32, 32, 1), 256, SMEM_DYN>>>(a);
    }
    {
        GArg a = {};
        a.A[0] = Ct; a.B[0] = tWo; a.bias[0] = tbo; a.C[0] = out; a.gate = G;
        a.M = 4096; a.N = 4096; a.K = 1024; a.Ksplit = 0;
        tgemm<3, false><<<dim3(32, 32, 1), 256, SMEM_DYN>>>(a);
    }

    (void)in_sizes; (void)n_in; (void)out_size;
}

// round 6
// speedup vs baseline: 1.4608x; 1.4608x over previous
#include <cuda_runtime.h>
#include <cstdint>

typedef unsigned long long u64;
typedef unsigned int u32;

// ---------------- packed fp32x2 helpers (attention kernel) ----------------
__device__ __forceinline__ u64 pack2(float x, float y) {
    u64 r; asm("mov.b64 %0, {%1, %2};" : "=l"(r) : "f"(x), "f"(y)); return r;
}
__device__ __forceinline__ float2 unpack2(u64 v) {
    float2 r; asm("mov.b64 {%0, %1}, %2;" : "=f"(r.x), "=f"(r.y) : "l"(v)); return r;
}
__device__ __forceinline__ void fma2(u64& d, u64 a, u64 b) {
    asm("fma.rn.f32x2 %0, %1, %2, %0;" : "+l"(d) : "l"(a), "l"(b));
}
__device__ __forceinline__ u64 mul2(u64 a, u64 b) {
    u64 d; asm("mul.rn.f32x2 %0, %1, %2;" : "=l"(d) : "l"(a), "l"(b)); return d;
}

// ---------------- bf16 helpers ----------------
// pack (k, k+1) -> bf16x2 word, low half = vk (first source of cvt goes HIGH)
__device__ __forceinline__ u32 packbf(float vk, float vk1) {
    u32 r; asm("cvt.rn.bf16x2.f32 %0, %1, %2;" : "=r"(r) : "f"(vk1), "f"(vk));
    return r;
}
__device__ __forceinline__ float bf_lo_f(u32 w) { return __uint_as_float(w << 16); }
__device__ __forceinline__ float bf_hi_f(u32 w) { return __uint_as_float(w & 0xffff0000u); }

// m16n8k16 bf16 MMA, row.col, fp32 accumulate (baseline PTX, sm_80+)
__device__ __forceinline__ void mma16(float* c, u32 a0, u32 a1, u32 a2, u32 a3,
                                      u32 b0, u32 b1) {
    asm volatile("mma.sync.aligned.m16n8k16.row.col.f32.bf16.bf16.f32 "
                 "{%0,%1,%2,%3}, {%4,%5,%6,%7}, {%8,%9}, {%0,%1,%2,%3};"
                 : "+f"(c[0]), "+f"(c[1]), "+f"(c[2]), "+f"(c[3])
                 : "r"(a0), "r"(a1), "r"(a2), "r"(a3), "r"(b0), "r"(b1));
}

// ---------------- scratch (device globals: allocation-free) ----------------
__device__ float g_Qt[4096 * 1024];
__device__ float g_Qd[4096 * 1024];
__device__ float g_Kt[1024 * 1024];
__device__ float g_Vt[1024 * 1024];
__device__ float g_Kd[1024 * 1024];
__device__ float g_Vd[1024 * 1024];
__device__ float g_Ct[4096 * 1024];
__device__ float g_Cd[4096 * 1024];
__device__ float g_H [4096 * 1024];
__device__ float g_gate[4096];

// ---------------- multi-operand GEMM argument block ----------------
struct GArg {
    const float* A[4];
    const float* A2[4];   // second K-segment source (DUAL only)
    const float* B[4];
    const float* bias[4];
    float*       C[4];
    const float* gate;
    int M, N, K, Ksplit;
};

// ---------------- HMMA 3xBF16 GEMM, 128x128 tile, k-stage 16 ----------------
// x = hi + lo (both bf16); D += Ah*Bh + Ah*Bl + Al*Bh  (fp32 accumulate)
// EPI 0: C = AB + bias
// EPI 1: C = relu(AB + bias)                  (with DUAL-A K concat)
// EPI 3: C = C + gate[r]*((AB + bias) - C)
//
// SMEM per stage buffer (u32 words = bf16x2 along k):
//  Ah[1280] Al[1280] Bh[1280] Bl[1280]   (row/col stride 10 words = 40B)
//  word order within row permuted: pos = 2*(w&3) + (w>>2)  so that the
//  fragment pair (w=tq, w=tq+4) is one aligned LDS.64 at pos 2*tq.
static constexpr int PLN  = 1280;           // u32 per plane
static constexpr int BUFU = 4 * PLN;        // 5120 u32 per buffer
static constexpr int SMEM_DYN = 2 * BUFU * 4;   // 40960 bytes

__device__ __forceinline__ int perm8(int w) { return 2 * (w & 3) + (w >> 2); }

template<int EPI, bool DUAL>
__global__ __launch_bounds__(256, 2)
void tgemm(GArg g)
{
    extern __shared__ __align__(16) u32 smu[];

    const int tid  = threadIdx.x;
    const int wid  = tid >> 5;
    const int lane = tid & 31;
    const int gq   = lane >> 2;      // 0..7
    const int tq   = lane & 3;       // 0..3
    const int wr   = (wid & 1) * 64; // warp row offset
    const int wc   = (wid >> 1) * 32;// warp col offset

    const int z = blockIdx.z;
    const float* __restrict__ A    = g.A[z];
    const float* __restrict__ A2   = g.A2[z];
    const float* __restrict__ B    = g.B[z];
    const float* __restrict__ bias = g.bias[z];
    float* __restrict__ C          = g.C[z];
    const int M = g.M, N = g.N, K = g.K, Ksp = g.Ksplit;
    const int lda = DUAL ? Ksp : K;
    const int row0 = blockIdx.y * 128;
    const int col0 = blockIdx.x * 128;

    float acc[4][4][4];
    #pragma unroll
    for (int i = 0; i < 4; i++)
        #pragma unroll
        for (int j = 0; j < 4; j++)
            #pragma unroll
            for (int q = 0; q < 4; q++) acc[i][j][q] = 0.f;

    // ldg staging
    float4 aR[2], bRe, bRo;
    const int aRow = tid >> 2;       // 0..63 (it adds 64)
    const int aC4  = tid & 3;        // k quarter
    const int bKp  = tid >> 5;       // k-pair 0..7
    const int bNq  = tid & 31;       // col quad

    auto ldg_stage = [&](int k0) {
        #pragma unroll
        for (int it = 0; it < 2; it++) {
            int r = aRow + it * 64;
            int gr = row0 + r;
            int kk = k0 + aC4 * 4;
            const float* base = A;
            if (DUAL && kk >= Ksp) { base = A2; kk -= Ksp; }
            aR[it] = (gr < M) ? *(const float4*)(base + (size_t)gr * lda + kk)
                              : make_float4(0.f, 0.f, 0.f, 0.f);
        }
        bRe = *(const float4*)(B + (size_t)(k0 + 2 * bKp)     * N + col0 + bNq * 4);
        bRo = *(const float4*)(B + (size_t)(k0 + 2 * bKp + 1) * N + col0 + bNq * 4);
    };

    auto sts_stage = [&](int buf) {
        u32* Ah = smu + buf * BUFU;
        u32* Al = Ah + PLN;
        u32* Bh = Ah + 2 * PLN;
        u32* Bl = Ah + 3 * PLN;
        // A: each thread wrote rows aRow, aRow+64, k = aC4*4 .. +3 -> words 2*aC4, 2*aC4+1
        #pragma unroll
        for (int it = 0; it < 2; it++) {
            int r = aRow + it * 64;
            float v[4] = { aR[it].x, aR[it].y, aR[it].z, aR[it].w };
            #pragma unroll
            for (int p = 0; p < 2; p++) {
                u32 hw = packbf(v[p * 2], v[p * 2 + 1]);
                float l0 = v[p * 2]     - bf_lo_f(hw);
                float l1 = v[p * 2 + 1] - bf_hi_f(hw);
                u32 lw = packbf(l0, l1);
                int off = r * 10 + perm8(2 * aC4 + p);
                Ah[off] = hw;
                Al[off] = lw;
            }
        }
        // B: thread has (k0+2*bKp, k0+2*bKp+1) x 4 cols -> word bKp per col
        {
            float e[4] = { bRe.x, bRe.y, bRe.z, bRe.w };
            float o[4] = { bRo.x, bRo.y, bRo.z, bRo.w };
            #pragma unroll
            for (int c = 0; c < 4; c++) {
                int n = bNq * 4 + c;
                u32 hw = packbf(e[c], o[c]);
                float l0 = e[c] - bf_lo_f(hw);
                float l1 = o[c] - bf_hi_f(hw);
                u32 lw = packbf(l0, l1);
                int off = n * 10 + perm8(bKp);
                Bh[off] = hw;
                Bl[off] = lw;
            }
        }
    };

    auto ld_af = [&](const u32* pl, u32 af[4][4]) {
        #pragma unroll
        for (int mi = 0; mi < 4; mi++) {
            int r0 = wr + mi * 16 + gq;
            u64 p0 = *(const u64*)(pl + r0 * 10 + 2 * tq);
            u64 p1 = *(const u64*)(pl + (r0 + 8) * 10 + 2 * tq);
            af[mi][0] = (u32)p0;          // row gq,   k=2tq..2tq+1
            af[mi][2] = (u32)(p0 >> 32);  // row gq,   k=2tq+8..+9
            af[mi][1] = (u32)p1;          // row gq+8, k=2tq..
            af[mi][3] = (u32)(p1 >> 32);  // row gq+8, k=2tq+8..
        }
    };
    auto ld_bf = [&](const u32* pl, u32 bf[4][2]) {
        #pragma unroll
        for (int ni = 0; ni < 4; ni++) {
            int c = wc + ni * 8 + gq;
            u64 p = *(const u64*)(pl + c * 10 + 2 * tq);
            bf[ni][0] = (u32)p;           // k=2tq..2tq+1
            bf[ni][1] = (u32)(p >> 32);   // k=2tq+8..+9
        }
    };

    auto compute = [&](int buf) {
        const u32* fb = smu + buf * BUFU;
        u32 af[4][4], bfh[4][2], bfl[4][2];
        ld_af(fb, af);                    // Ah
        ld_bf(fb + 2 * PLN, bfh);         // Bh
        #pragma unroll
        for (int mi = 0; mi < 4; mi++)
            #pragma unroll
            for (int ni = 0; ni < 4; ni++)
                mma16(acc[mi][ni], af[mi][0], af[mi][1], af[mi][2], af[mi][3],
                      bfh[ni][0], bfh[ni][1]);
        ld_bf(fb + 3 * PLN, bfl);         // Bl
        #pragma unroll
        for (int mi = 0; mi < 4; mi++)
            #pragma unroll
            for (int ni = 0; ni < 4; ni++)
                mma16(acc[mi][ni], af[mi][0], af[mi][1], af[mi][2], af[mi][3],
                      bfl[ni][0], bfl[ni][1]);
        ld_af(fb + PLN, af);              // Al (reuse af regs)
        #pragma unroll
        for (int mi = 0; mi < 4; mi++)
            #pragma unroll
            for (int ni = 0; ni < 4; ni++)
                mma16(acc[mi][ni], af[mi][0], af[mi][1], af[mi][2], af[mi][3],
                      bfh[ni][0], bfh[ni][1]);
    };

    // prologue
    ldg_stage(0);
    sts_stage(0);
    __syncthreads();

    const int nst = K / 16;
    for (int s = 0; s < nst; s++) {
        const int buf = s & 1;
        if (s + 1 < nst) ldg_stage((s + 1) * 16);
        compute(buf);
        if (s + 1 < nst) sts_stage(buf ^ 1);
        __syncthreads();
    }

    // epilogue: acc -> C   (c0,c1 @ (row gq, col 2tq); c2,c3 @ (row gq+8))
    #pragma unroll
    for (int mi = 0; mi < 4; mi++) {
        #pragma unroll
        for (int rr = 0; rr < 2; rr++) {
            int r = row0 + wr + mi * 16 + gq + rr * 8;
            if (r >= M) continue;
            float gg = (EPI == 3) ? g.gate[r] : 0.f;
            #pragma unroll
            for (int ni = 0; ni < 4; ni++) {
                int c = col0 + wc + ni * 8 + tq * 2;
                size_t idx = (size_t)r * N + c;
                float s0 = acc[mi][ni][rr * 2 + 0] + bias[c];
                float s1 = acc[mi][ni][rr * 2 + 1] + bias[c + 1];
                float2 o;
                if (EPI == 0) {
                    o = make_float2(s0, s1);
                } else if (EPI == 1) {
                    o = make_float2(fmaxf(s0, 0.f), fmaxf(s1, 0.f));
                } else {
                    float2 old = *(const float2*)(C + idx);
                    o = make_float2(old.x + gg * (s0 - old.x),
                                    old.y + gg * (s1 - old.y));
                }
                *(float2*)(C + idx) = o;
            }
        }
    }
}

// ---------------- flash attention: 1 thread per query row, online softmax ----
struct FArg {
    const float* Q[2];
    const float* Kb[2];
    const float* Vb[2];
    float*       O[2];
};

__global__ __launch_bounds__(64)
void flash_attn(FArg f, int S)
{
    __shared__ __align__(16) u64 Ks[64 * 32];
    __shared__ __align__(16) u64 Vs[64 * 32];
    __shared__ float Ss[64 * 64];
    const int tid = threadIdx.x;
    const int h   = blockIdx.y;
    const int sel = blockIdx.z >> 3;
    const int b   = blockIdx.z & 7;
    const int row = b * 512 + blockIdx.x * 64 + tid;

    const float* __restrict__ Q  = f.Q[sel];
    const float* __restrict__ Kb = f.Kb[sel];
    const float* __restrict__ Vb = f.Vb[sel];
    float* __restrict__ O        = f.O[sel];

    const u64* qp = (const u64*)(Q + (size_t)row * 1024 + h * 64);
    u64 q2[32];
    #pragma unroll
    for (int i = 0; i < 32; i++) q2[i] = qp[i];

    u64 acc2[32] = {};
    float m = -1e30f, lsum = 0.f;
    const float scale = 0.125f;

    for (int s0 = 0; s0 < S; s0 += 64) {
        int jmax = S - s0; if (jmax > 64) jmax = 64;
        #pragma unroll
        for (int i = 0; i < 32; i++) {
            int idx = i * 64 + tid;
            int j = idx >> 5, e2 = idx & 31;
            int srow = s0 + j;
            u64 kv = 0, vv = 0;
            if (srow < S) {
                kv = ((const u64*)(Kb + (size_t)srow * 1024 + h * 64))[e2];
                vv = ((const u64*)(Vb + (size_t)srow * 1024 + h * 64))[e2];
            }
            Ks[idx] = kv; Vs[idx] = vv;
        }
        __syncthreads();

        float tmax = -1e30f;
        for (int j = 0; j < 64; j++) {
            float s;
            if (j < jmax) {
                u64 s2 = 0;
                const ulonglong2* kp = (const ulonglong2*)&Ks[j * 32];
                #pragma unroll
                for (int e = 0; e < 16; e++) {
                    ulonglong2 kv = kp[e];
                    fma2(s2, q2[e * 2],     kv.x);
                    fma2(s2, q2[e * 2 + 1], kv.y);
                }
                float2 sf = unpack2(s2);
                s = (sf.x + sf.y) * scale;
            } else {
                s = -1e30f;
            }
            tmax = fmaxf(tmax, s);
            Ss[j * 64 + tid] = s;
        }

        float mnew  = fmaxf(m, tmax);
        float alpha = __expf(m - mnew);
        lsum *= alpha;
        u64 a2 = pack2(alpha, alpha);
        #pragma unroll
        for (int e = 0; e < 32; e++) acc2[e] = mul2(acc2[e], a2);

        for (int j = 0; j < 64; j++) {
            float p = __expf(Ss[j * 64 + tid] - mnew);
            lsum += p;
            u64 p2 = pack2(p, p);
            const ulonglong2* vp = (const ulonglong2*)&Vs[j * 32];
            #pragma unroll
            for (int e = 0; e < 16; e++) {
                ulonglong2 vv = vp[e];
                fma2(acc2[e * 2],     p2, vv.x);
                fma2(acc2[e * 2 + 1], p2, vv.y);
            }
        }
        m = mnew;
        __syncthreads();
    }

    float inv = 1.f / lsum;
    float2* op = (float2*)(O + (size_t)row * 1024 + h * 64);
    #pragma unroll
    for (int e = 0; e < 32; e++) {
        float2 v = unpack2(acc2[e]);
        v.x *= inv; v.y *= inv;
        op[e] = v;
    }
}

// ---------------- gate: G[r] = sigmoid(H[r,:] . W2 + b2), one warp per row ----
__global__ __launch_bounds__(256)
void gate_kernel(const float* __restrict__ H, const float* __restrict__ W2,
                 const float* __restrict__ b2, float* __restrict__ G)
{
    int w = (blockIdx.x * blockDim.x + threadIdx.x) >> 5;
    int lane = threadIdx.x & 31;
    const float* hp = H + (size_t)w * 1024;
    float s = 0.f;
    #pragma unroll
    for (int i = 0; i < 32; i++) s += hp[lane + i * 32] * W2[lane + i * 32];
    #pragma unroll
    for (int o = 16; o; o >>= 1) s += __shfl_xor_sync(0xffffffffu, s, o);
    if (lane == 0) G[w] = 1.f / (1.f + __expf(-(s + b2[0])));
}

// ---------------- launch ----------------
extern "C" void kernel_launch(void* const* d_in, const int* in_sizes, int n_in,
                              void* d_out, int out_size)
{
    const float* trend  = (const float*)d_in[0];
    const float* detail = (const float*)d_in[1];
    const float* protoT = (const float*)d_in[2];
    const float* protoD = (const float*)d_in[3];
    const float* tWq = (const float*)d_in[4];  const float* tbq = (const float*)d_in[5];
    const float* tWk = (const float*)d_in[6];  const float* tbk = (const float*)d_in[7];
    const float* tWv = (const float*)d_in[8];  const float* tbv = (const float*)d_in[9];
    const float* tWo = (const float*)d_in[10]; const float* tbo = (const float*)d_in[11];
    const float* dWq = (const float*)d_in[12]; const float* dbq = (const float*)d_in[13];
    const float* dWk = (const float*)d_in[14]; const float* dbk = (const float*)d_in[15];
    const float* dWv = (const float*)d_in[16]; const float* dbv = (const float*)d_in[17];
    const float* dWo = (const float*)d_in[18]; const float* dbo = (const float*)d_in[19];
    const float* gW1 = (const float*)d_in[20]; const float* gb1 = (const float*)d_in[21];
    const float* gW2 = (const float*)d_in[22]; const float* gb2 = (const float*)d_in[23];
    float* out = (float*)d_out;

    float *Qt, *Qd, *Kt, *Vt, *Kd, *Vd, *Ct, *Cd, *H, *G;
    cudaGetSymbolAddress((void**)&Qt, g_Qt);
    cudaGetSymbolAddress((void**)&Qd, g_Qd);
    cudaGetSymbolAddress((void**)&Kt, g_Kt);
    cudaGetSymbolAddress((void**)&Vt, g_Vt);
    cudaGetSymbolAddress((void**)&Kd, g_Kd);
    cudaGetSymbolAddress((void**)&Vd, g_Vd);
    cudaGetSymbolAddress((void**)&Ct, g_Ct);
    cudaGetSymbolAddress((void**)&Cd, g_Cd);
    cudaGetSymbolAddress((void**)&H,  g_H);
    cudaGetSymbolAddress((void**)&G,  g_gate);

    cudaFuncSetAttribute(tgemm<0, false>, cudaFuncAttributeMaxDynamicSharedMemorySize, SMEM_DYN);
    cudaFuncSetAttribute(tgemm<1, true >, cudaFuncAttributeMaxDynamicSharedMemorySize, SMEM_DYN);
    cudaFuncSetAttribute(tgemm<3, false>, cudaFuncAttributeMaxDynamicSharedMemorySize, SMEM_DYN);

    // 1) Q projections, merged (z=2)
    {
        GArg a = {};
        a.A[0] = trend;  a.B[0] = tWq; a.bias[0] = tbq; a.C[0] = Qt;
        a.A[1] = detail; a.B[1] = dWq; a.bias[1] = dbq; a.C[1] = Qd;
        a.M = 4096; a.N = 1024; a.K = 1024; a.Ksplit = 0;
        tgemm<0, false><<<dim3(8, 32, 2), 256, SMEM_DYN>>>(a);
    }
    // 2) K/V projections, merged (z=4)
    {
        GArg a = {};
        a.A[0] = protoT; a.B[0] = tWk; a.bias[0] = tbk; a.C[0] = Kt;
        a.A[1] = protoT; a.B[1] = tWv; a.bias[1] = tbv; a.C[1] = Vt;
        a.A[2] = protoD; a.B[2] = dWk; a.bias[2] = dbk; a.C[2] = Kd;
        a.A[3] = protoD; a.B[3] = dWv; a.bias[3] = dbv; a.C[3] = Vd;
        a.M = 1000; a.N = 1024; a.K = 4096; a.Ksplit = 0;
        tgemm<0, false><<<dim3(8, 8, 4), 256, SMEM_DYN>>>(a);
    }
    // 3) attention, both branches merged
    {
        FArg fa = {};
        fa.Q[0] = Qt; fa.Kb[0] = Kt; fa.Vb[0] = Vt; fa.O[0] = Ct;
        fa.Q[1] = Qd; fa.Kb[1] = Kd; fa.Vb[1] = Vd; fa.O[1] = Cd;
        flash_attn<<<dim3(8, 16, 16), 64>>>(fa, 1000);
    }
    // 4) gate MLP layer 1: H = relu([trend|detail] @ gW1 + gb1)
    {
        GArg a = {};
        a.A[0] = trend; a.A2[0] = detail; a.B[0] = gW1; a.bias[0] = gb1; a.C[0] = H;
        a.M = 4096; a.N = 1024; a.K = 2048; a.Ksplit = 1024;
        tgemm<1, true><<<dim3(8, 32, 1), 256, SMEM_DYN>>>(a);
    }
    // 5) gate
    gate_kernel<<<512, 256>>>(H, gW2, gb2, G);

    // 6) output projections + fused blend
    {
        GArg a = {};
        a.A[0] = Cd; a.B[0] = dWo; a.bias[0] = dbo; a.C[0] = out;
        a.M = 4096; a.N = 4096; a.K = 1024; a.Ksplit = 0;
        tgemm<0, false><<<dim3(32, 32, 1), 256, SMEM_DYN>>>(a);
    }
    {
        GArg a = {};
        a.A[0] = Ct; a.B[0] = tWo; a.bias[0] = tbo; a.C[0] = out; a.gate = G;
        a.M = 4096; a.N = 4096; a.K = 1024; a.Ksplit = 0;
        tgemm<3, false><<<dim3(32, 32, 1), 256, SMEM_DYN>>>(a);
    }

    (void)in_sizes; (void)n_in; (void)out_size;
}

// round 7
// speedup vs baseline: 1.6029x; 1.0973x over previous
#include <cuda_runtime.h>
#include <cuda_bf16.h>
#include <cstdint>

typedef unsigned long long u64;
typedef unsigned int u32;
typedef unsigned short u16;

// ---------------- packed fp32x2 helpers (attention kernel) ----------------
__device__ __forceinline__ u64 pack2(float x, float y) {
    u64 r; asm("mov.b64 %0, {%1, %2};" : "=l"(r) : "f"(x), "f"(y)); return r;
}
__device__ __forceinline__ float2 unpack2(u64 v) {
    float2 r; asm("mov.b64 {%0, %1}, %2;" : "=f"(r.x), "=f"(r.y) : "l"(v)); return r;
}
__device__ __forceinline__ void fma2(u64& d, u64 a, u64 b) {
    asm("fma.rn.f32x2 %0, %1, %2, %0;" : "+l"(d) : "l"(a), "l"(b));
}
__device__ __forceinline__ u64 mul2(u64 a, u64 b) {
    u64 d; asm("mul.rn.f32x2 %0, %1, %2;" : "=l"(d) : "l"(a), "l"(b)); return d;
}

// ---------------- bf16 helpers ----------------
// pack (v0, v1) -> bf16x2 word, memory order: low half = v0
__device__ __forceinline__ u32 packbf(float v0, float v1) {
    u32 r; asm("cvt.rn.bf16x2.f32 %0, %1, %2;" : "=r"(r) : "f"(v1), "f"(v0));
    return r;
}
__device__ __forceinline__ float bf_lo_f(u32 w) { return __uint_as_float(w << 16); }
__device__ __forceinline__ float bf_hi_f(u32 w) { return __uint_as_float(w & 0xffff0000u); }

// m16n8k16 bf16 MMA, row.col, fp32 accumulate
__device__ __forceinline__ void mma16(float* c, u32 a0, u32 a1, u32 a2, u32 a3,
                                      u32 b0, u32 b1) {
    asm volatile("mma.sync.aligned.m16n8k16.row.col.f32.bf16.bf16.f32 "
                 "{%0,%1,%2,%3}, {%4,%5,%6,%7}, {%8,%9}, {%0,%1,%2,%3};"
                 : "+f"(c[0]), "+f"(c[1]), "+f"(c[2]), "+f"(c[3])
                 : "r"(a0), "r"(a1), "r"(a2), "r"(a3), "r"(b0), "r"(b1));
}

// ---------------- cp.async / ldmatrix ----------------
__device__ __forceinline__ u32 smem_u32(const void* p) {
    u32 a; asm("{ .reg .u64 t; cvta.to.shared.u64 t, %1; cvt.u32.u64 %0, t; }"
                : "=r"(a) : "l"(p));
    return a;
}
__device__ __forceinline__ void cpasync16(u32 dst, const void* src, int srcsize) {
    asm volatile("cp.async.cg.shared.global [%0], [%1], 16, %2;"
                 :: "r"(dst), "l"(src), "r"(srcsize) : "memory");
}
__device__ __forceinline__ void cpcommit() {
    asm volatile("cp.async.commit_group;" ::: "memory");
}
template<int N> __device__ __forceinline__ void cpwait() {
    asm volatile("cp.async.wait_group %0;" :: "n"(N) : "memory");
}
__device__ __forceinline__ void ldsm4(u32& r0, u32& r1, u32& r2, u32& r3, u32 addr) {
    asm volatile("ldmatrix.sync.aligned.m8n8.x4.shared.b16 {%0,%1,%2,%3}, [%4];"
                 : "=r"(r0), "=r"(r1), "=r"(r2), "=r"(r3) : "r"(addr));
}

// ---------------- scratch (device globals: allocation-free) ----------------
// fp32 intermediates
__device__ float g_Qt[4096 * 1024];
__device__ float g_Qd[4096 * 1024];
__device__ float g_Kt[1024 * 1024];
__device__ float g_Vt[1024 * 1024];
__device__ float g_Kd[1024 * 1024];
__device__ float g_Vd[1024 * 1024];
__device__ float g_H [4096 * 1024];
__device__ float g_gate[4096];
// bf16 hi/lo planes: A-side inputs
__device__ u16 g_trH[4096 * 1024], g_trL[4096 * 1024];
__device__ u16 g_deH[4096 * 1024], g_deL[4096 * 1024];
__device__ u16 g_pTH[1000 * 4096], g_pTL[1000 * 4096];
__device__ u16 g_pDH[1000 * 4096], g_pDL[1000 * 4096];
// attention outputs (A-side of out-projection)
__device__ u16 g_ctH[4096 * 1024], g_ctL[4096 * 1024];
__device__ u16 g_cdH[4096 * 1024], g_cdL[4096 * 1024];
// weights, stored transposed [N,K]
__device__ u16 g_wqtH[1024 * 1024], g_wqtL[1024 * 1024];
__device__ u16 g_wqdH[1024 * 1024], g_wqdL[1024 * 1024];
__device__ u16 g_wktH[1024 * 4096], g_wktL[1024 * 4096];
__device__ u16 g_wvtH[1024 * 4096], g_wvtL[1024 * 4096];
__device__ u16 g_wkdH[1024 * 4096], g_wkdL[1024 * 4096];
__device__ u16 g_wvdH[1024 * 4096], g_wvdL[1024 * 4096];
__device__ u16 g_wotH[4096 * 1024], g_wotL[4096 * 1024];
__device__ u16 g_wodH[4096 * 1024], g_wodL[4096 * 1024];
__device__ u16 g_gw1H[1024 * 2048], g_gw1L[1024 * 2048];

// ---------------- pre-pass: elementwise fp32 -> bf16 hi/lo ----------------
struct CArg { const float* src[4]; u32* dH[4]; u32* dL[4]; int n2[4]; };
__global__ __launch_bounds__(256)
void convA(CArg c)
{
    int z = blockIdx.y;
    int i = blockIdx.x * 256 + threadIdx.x;
    if (i >= c.n2[z]) return;
    float2 v = ((const float2*)c.src[z])[i];
    u32 hw = packbf(v.x, v.y);
    float l0 = v.x - bf_lo_f(hw);
    float l1 = v.y - bf_hi_f(hw);
    c.dH[z][i] = hw;
    c.dL[z][i] = packbf(l0, l1);
}

// ---------------- pre-pass: transpose [K,N] fp32 -> [N,K] bf16 hi/lo -------
struct TArg { const float* src[9]; u16* dH[9]; u16* dL[9]; int K[9]; int N[9]; };
__global__ __launch_bounds__(256)
void convB(TArg t)
{
    __shared__ float tile[32][33];
    int z = blockIdx.z;
    int K = t.K[z], N = t.N[z];
    int k0 = blockIdx.x * 32, n0 = blockIdx.y * 32;
    if (k0 >= K || n0 >= N) return;
    const float* src = t.src[z];
    #pragma unroll
    for (int r = 0; r < 4; r++)
        tile[threadIdx.y + r * 8][threadIdx.x] =
            src[(size_t)(k0 + threadIdx.y + r * 8) * N + n0 + threadIdx.x];
    __syncthreads();
    u16* dH = t.dH[z]; u16* dL = t.dL[z];
    #pragma unroll
    for (int r = 0; r < 4; r++) {
        int n = n0 + threadIdx.y + r * 8;
        int k = k0 + threadIdx.x;
        float v = tile[threadIdx.x][threadIdx.y + r * 8];
        __nv_bfloat16 h = __float2bfloat16(v);
        float hf = __bfloat162float(h);
        __nv_bfloat16 l = __float2bfloat16(v - hf);
        dH[(size_t)n * K + k] = *(u16*)&h;
        dL[(size_t)n * K + k] = *(u16*)&l;
    }
}

// ---------------- GEMM argument block ----------------
struct GArg {
    const u16* AH[4]; const u16* AL[4];
    const u16* A2H[4]; const u16* A2L[4];   // DUAL second K-segment
    const u16* BH[4]; const u16* BL[4];     // [N,K] layout
    const float* bias[4];
    float* C[4];
    const float* gate;
    int M, N, K, Ksplit;
};

// ---------------- HMMA 3xBF16 GEMM: cp.async + ldmatrix core ----------------
// D += Ah*Bh + Ah*Bl + Al*Bh, fp32 accum. 128x128 CTA tile, k-stage 16.
// SMEM per stage: 4 planes (Ah, Al, Bh, Bl), each 128 rows x 48B (16 k bf16 + pad).
// 48B stride -> ldmatrix rows hit a perfect 32-bank partition (conflict-free).
static constexpr int ROWB   = 48;
static constexpr int PLANEB = 128 * ROWB;        // 6144
static constexpr int STAGEB = 4 * PLANEB;        // 24576
static constexpr int SMEM_DYN = 2 * STAGEB;      // 49152

template<int EPI, bool DUAL>
__global__ __launch_bounds__(256, 2)
void tgemm(GArg g)
{
    extern __shared__ __align__(16) char smem[];
    const u32 sb = smem_u32(smem);

    const int tid  = threadIdx.x;
    const int wid  = tid >> 5;
    const int lane = tid & 31;
    const int gq   = lane >> 2;
    const int tq   = lane & 3;
    const int wr   = (wid & 1) * 64;
    const int wc   = (wid >> 1) * 32;

    const int z = blockIdx.z;
    const u16* __restrict__ AH  = g.AH[z];
    const u16* __restrict__ AL  = g.AL[z];
    const u16* __restrict__ A2H = g.A2H[z];
    const u16* __restrict__ A2L = g.A2L[z];
    const u16* __restrict__ BH  = g.BH[z];
    const u16* __restrict__ BL  = g.BL[z];
    const float* __restrict__ bias = g.bias[z];
    float* __restrict__ C          = g.C[z];
    const int M = g.M, N = g.N, K = g.K, Ksp = g.Ksplit;
    const int lda = DUAL ? Ksp : K;
    const int row0 = blockIdx.y * 128;
    const int col0 = blockIdx.x * 128;

    float acc[4][4][4];
    #pragma unroll
    for (int i = 0; i < 4; i++)
        #pragma unroll
        for (int j = 0; j < 4; j++)
            #pragma unroll
            for (int q = 0; q < 4; q++) acc[i][j][q] = 0.f;

    // loader: 256 threads, 1 chunk (16B) per plane per thread per stage
    const int cRow  = tid >> 1;
    const int cHalf = tid & 1;

    auto issue = [&](int s, int buf) {
        const int k0 = s * 16;
        const u32 dbase = sb + buf * STAGEB + cRow * ROWB + cHalf * 16;
        // A planes
        {
            int kk = k0 + cHalf * 8;
            const u16* bh = AH; const u16* bl = AL;
            if (DUAL && kk >= Ksp) { bh = A2H; bl = A2L; kk -= Ksp; }
            int gr = row0 + cRow;
            int ok = (gr < M) ? 16 : 0;
            int grc = (gr < M) ? gr : (M - 1);
            cpasync16(dbase,              bh + (size_t)grc * lda + kk, ok);
            cpasync16(dbase + PLANEB,     bl + (size_t)grc * lda + kk, ok);
        }
        // B planes ([N,K], N multiple of 128 -> no guard)
        {
            int kk = k0 + cHalf * 8;
            size_t off = (size_t)(col0 + cRow) * K + kk;
            cpasync16(dbase + 2 * PLANEB, BH + off, 16);
            cpasync16(dbase + 3 * PLANEB, BL + off, 16);
        }
    };

    // ldmatrix lane addressing
    const int lr = lane & 7;
    const int lb = (lane >> 3) & 1;
    const int lh = lane >> 4;
    const u32 aoff = (u32)((wr + lb * 8 + lr) * ROWB + lh * 16);
    const u32 boff = (u32)((wc + lh * 8 + lr) * ROWB + lb * 16) + 2 * PLANEB;

    auto compute = [&](int buf) {
        const u32 base = sb + buf * STAGEB;
        u32 ah[4][4], bh[4][2], bl[4][2];
        #pragma unroll
        for (int mi = 0; mi < 4; mi++)
            ldsm4(ah[mi][0], ah[mi][1], ah[mi][2], ah[mi][3],
                  base + aoff + mi * (16 * ROWB));
        #pragma unroll
        for (int nj = 0; nj < 2; nj++)
            ldsm4(bh[2 * nj][0], bh[2 * nj][1], bh[2 * nj + 1][0], bh[2 * nj + 1][1],
                  base + boff + nj * (16 * ROWB));
        #pragma unroll
        for (int mi = 0; mi < 4; mi++)
            #pragma unroll
            for (int ni = 0; ni < 4; ni++)
                mma16(acc[mi][ni], ah[mi][0], ah[mi][1], ah[mi][2], ah[mi][3],
                      bh[ni][0], bh[ni][1]);
        #pragma unroll
        for (int nj = 0; nj < 2; nj++)
            ldsm4(bl[2 * nj][0], bl[2 * nj][1], bl[2 * nj + 1][0], bl[2 * nj + 1][1],
                  base + boff + PLANEB + nj * (16 * ROWB));
        #pragma unroll
        for (int mi = 0; mi < 4; mi++)
            #pragma unroll
            for (int ni = 0; ni < 4; ni++)
                mma16(acc[mi][ni], ah[mi][0], ah[mi][1], ah[mi][2], ah[mi][3],
                      bl[ni][0], bl[ni][1]);
        #pragma unroll
        for (int mi = 0; mi < 4; mi++)          // reuse ah regs for Al
            ldsm4(ah[mi][0], ah[mi][1], ah[mi][2], ah[mi][3],
                  base + aoff + PLANEB + mi * (16 * ROWB));
        #pragma unroll
        for (int mi = 0; mi < 4; mi++)
            #pragma unroll
            for (int ni = 0; ni < 4; ni++)
                mma16(acc[mi][ni], ah[mi][0], ah[mi][1], ah[mi][2], ah[mi][3],
                      bh[ni][0], bh[ni][1]);
    };

    const int nst = K / 16;
    issue(0, 0); cpcommit();
    if (nst > 1) { issue(1, 1); cpcommit(); }

    for (int s = 0; s < nst; s++) {
        if (s + 1 < nst) cpwait<1>(); else cpwait<0>();
        __syncthreads();
        compute(s & 1);
        __syncthreads();
        if (s + 2 < nst) { issue(s + 2, s & 1); cpcommit(); }
    }

    // epilogue
    #pragma unroll
    for (int mi = 0; mi < 4; mi++) {
        #pragma unroll
        for (int rr = 0; rr < 2; rr++) {
            int r = row0 + wr + mi * 16 + gq + rr * 8;
            if (r >= M) continue;
            float gg = (EPI == 3) ? g.gate[r] : 0.f;
            #pragma unroll
            for (int ni = 0; ni < 4; ni++) {
                int c = col0 + wc + ni * 8 + tq * 2;
                size_t idx = (size_t)r * N + c;
                float s0 = acc[mi][ni][rr * 2 + 0] + bias[c];
                float s1 = acc[mi][ni][rr * 2 + 1] + bias[c + 1];
                float2 o;
                if (EPI == 0) {
                    o = make_float2(s0, s1);
                } else if (EPI == 1) {
                    o = make_float2(fmaxf(s0, 0.f), fmaxf(s1, 0.f));
                } else {
                    float2 old = *(const float2*)(C + idx);
                    o = make_float2(old.x + gg * (s0 - old.x),
                                    old.y + gg * (s1 - old.y));
                }
                *(float2*)(C + idx) = o;
            }
        }
    }
}

// ---------------- flash attention -> bf16 hi/lo output planes ----------------
struct FArg {
    const float* Q[2];
    const float* Kb[2];
    const float* Vb[2];
    u32* OH[2];
    u32* OL[2];
};

__global__ __launch_bounds__(64)
void flash_attn(FArg f, int S)
{
    __shared__ __align__(16) u64 Ks[64 * 32];
    __shared__ __align__(16) u64 Vs[64 * 32];
    __shared__ float Ss[64 * 64];
    const int tid = threadIdx.x;
    const int h   = blockIdx.y;
    const int sel = blockIdx.z >> 3;
    const int b   = blockIdx.z & 7;
    const int row = b * 512 + blockIdx.x * 64 + tid;

    const float* __restrict__ Q  = f.Q[sel];
    const float* __restrict__ Kb = f.Kb[sel];
    const float* __restrict__ Vb = f.Vb[sel];

    const u64* qp = (const u64*)(Q + (size_t)row * 1024 + h * 64);
    u64 q2[32];
    #pragma unroll
    for (int i = 0; i < 32; i++) q2[i] = qp[i];

    u64 acc2[32] = {};
    float m = -1e30f, lsum = 0.f;
    const float scale = 0.125f;

    for (int s0 = 0; s0 < S; s0 += 64) {
        int jmax = S - s0; if (jmax > 64) jmax = 64;
        #pragma unroll
        for (int i = 0; i < 32; i++) {
            int idx = i * 64 + tid;
            int j = idx >> 5, e2 = idx & 31;
            int srow = s0 + j;
            u64 kv = 0, vv = 0;
            if (srow < S) {
                kv = ((const u64*)(Kb + (size_t)srow * 1024 + h * 64))[e2];
                vv = ((const u64*)(Vb + (size_t)srow * 1024 + h * 64))[e2];
            }
            Ks[idx] = kv; Vs[idx] = vv;
        }
        __syncthreads();

        float tmax = -1e30f;
        for (int j = 0; j < 64; j++) {
            float s;
            if (j < jmax) {
                u64 s2 = 0;
                const ulonglong2* kp = (const ulonglong2*)&Ks[j * 32];
                #pragma unroll
                for (int e = 0; e < 16; e++) {
                    ulonglong2 kv = kp[e];
                    fma2(s2, q2[e * 2],     kv.x);
                    fma2(s2, q2[e * 2 + 1], kv.y);
                }
                float2 sf = unpack2(s2);
                s = (sf.x + sf.y) * scale;
            } else {
                s = -1e30f;
            }
            tmax = fmaxf(tmax, s);
            Ss[j * 64 + tid] = s;
        }

        float mnew  = fmaxf(m, tmax);
        float alpha = __expf(m - mnew);
        lsum *= alpha;
        u64 a2 = pack2(alpha, alpha);
        #pragma unroll
        for (int e = 0; e < 32; e++) acc2[e] = mul2(acc2[e], a2);

        for (int j = 0; j < 64; j++) {
            float p = __expf(Ss[j * 64 + tid] - mnew);
            lsum += p;
            u64 p2 = pack2(p, p);
            const ulonglong2* vp = (const ulonglong2*)&Vs[j * 32];
            #pragma unroll
            for (int e = 0; e < 16; e++) {
                ulonglong2 vv = vp[e];
                fma2(acc2[e * 2],     p2, vv.x);
                fma2(acc2[e * 2 + 1], p2, vv.y);
            }
        }
        m = mnew;
        __syncthreads();
    }

    float inv = 1.f / lsum;
    u32* OH = f.OH[sel];
    u32* OL = f.OL[sel];
    size_t obase = (size_t)row * 512 + h * 32;
    #pragma unroll
    for (int e = 0; e < 32; e++) {
        float2 v = unpack2(acc2[e]);
        v.x *= inv; v.y *= inv;
        u32 hw = packbf(v.x, v.y);
        float l0 = v.x - bf_lo_f(hw);
        float l1 = v.y - bf_hi_f(hw);
        OH[obase + e] = hw;
        OL[obase + e] = packbf(l0, l1);
    }
}

// ---------------- gate: G[r] = sigmoid(H[r,:] . W2 + b2), one warp per row ----
__global__ __launch_bounds__(256)
void gate_kernel(const float* __restrict__ H, const float* __restrict__ W2,
                 const float* __restrict__ b2, float* __restrict__ G)
{
    int w = (blockIdx.x * blockDim.x + threadIdx.x) >> 5;
    int lane = threadIdx.x & 31;
    const float* hp = H + (size_t)w * 1024;
    float s = 0.f;
    #pragma unroll
    for (int i = 0; i < 32; i++) s += hp[lane + i * 32] * W2[lane + i * 32];
    #pragma unroll
    for (int o = 16; o; o >>= 1) s += __shfl_xor_sync(0xffffffffu, s, o);
    if (lane == 0) G[w] = 1.f / (1.f + __expf(-(s + b2[0])));
}

// ---------------- launch ----------------
extern "C" void kernel_launch(void* const* d_in, const int* in_sizes, int n_in,
                              void* d_out, int out_size)
{
    const float* trend  = (const float*)d_in[0];
    const float* detail = (const float*)d_in[1];
    const float* protoT = (const float*)d_in[2];
    const float* protoD = (const float*)d_in[3];
    const float* tWq = (const float*)d_in[4];  const float* tbq = (const float*)d_in[5];
    const float* tWk = (const float*)d_in[6];  const float* tbk = (const float*)d_in[7];
    const float* tWv = (const float*)d_in[8];  const float* tbv = (const float*)d_in[9];
    const float* tWo = (const float*)d_in[10]; const float* tbo = (const float*)d_in[11];
    const float* dWq = (const float*)d_in[12]; const float* dbq = (const float*)d_in[13];
    const float* dWk = (const float*)d_in[14]; const float* dbk = (const float*)d_in[15];
    const float* dWv = (const float*)d_in[16]; const float* dbv = (const float*)d_in[17];
    const float* dWo = (const float*)d_in[18]; const float* dbo = (const float*)d_in[19];
    const float* gW1 = (const float*)d_in[20]; const float* gb1 = (const float*)d_in[21];
    const float* gW2 = (const float*)d_in[22]; const float* gb2 = (const float*)d_in[23];
    float* out = (float*)d_out;

    #define SYM(T, v, s) T* v; cudaGetSymbolAddress((void**)&v, s)
    SYM(float, Qt, g_Qt);   SYM(float, Qd, g_Qd);
    SYM(float, Kt, g_Kt);   SYM(float, Vt, g_Vt);
    SYM(float, Kd, g_Kd);   SYM(float, Vd, g_Vd);
    SYM(float, H,  g_H);    SYM(float, G,  g_gate);
    SYM(u16, trH, g_trH);   SYM(u16, trL, g_trL);
    SYM(u16, deH, g_deH);   SYM(u16, deL, g_deL);
    SYM(u16, pTH, g_pTH);   SYM(u16, pTL, g_pTL);
    SYM(u16, pDH, g_pDH);   SYM(u16, pDL, g_pDL);
    SYM(u16, ctH, g_ctH);   SYM(u16, ctL, g_ctL);
    SYM(u16, cdH, g_cdH);   SYM(u16, cdL, g_cdL);
    SYM(u16, wqtH, g_wqtH); SYM(u16, wqtL, g_wqtL);
    SYM(u16, wqdH, g_wqdH); SYM(u16, wqdL, g_wqdL);
    SYM(u16, wktH, g_wktH); SYM(u16, wktL, g_wktL);
    SYM(u16, wvtH, g_wvtH); SYM(u16, wvtL, g_wvtL);
    SYM(u16, wkdH, g_wkdH); SYM(u16, wkdL, g_wkdL);
    SYM(u16, wvdH, g_wvdH); SYM(u16, wvdL, g_wvdL);
    SYM(u16, wotH, g_wotH); SYM(u16, wotL, g_wotL);
    SYM(u16, wodH, g_wodH); SYM(u16, wodL, g_wodL);
    SYM(u16, gw1H, g_gw1H); SYM(u16, gw1L, g_gw1L);
    #undef SYM

    cudaFuncSetAttribute(tgemm<0, false>, cudaFuncAttributeMaxDynamicSharedMemorySize, SMEM_DYN);
    cudaFuncSetAttribute(tgemm<1, true >, cudaFuncAttributeMaxDynamicSharedMemorySize, SMEM_DYN);
    cudaFuncSetAttribute(tgemm<3, false>, cudaFuncAttributeMaxDynamicSharedMemorySize, SMEM_DYN);

    // 0a) A-side conversions
    {
        CArg c = {};
        c.src[0] = trend;  c.dH[0] = (u32*)trH; c.dL[0] = (u32*)trL; c.n2[0] = 4096 * 512;
        c.src[1] = detail; c.dH[1] = (u32*)deH; c.dL[1] = (u32*)deL; c.n2[1] = 4096 * 512;
        c.src[2] = protoT; c.dH[2] = (u32*)pTH; c.dL[2] = (u32*)pTL; c.n2[2] = 1000 * 2048;
        c.src[3] = protoD; c.dH[3] = (u32*)pDH; c.dL[3] = (u32*)pDL; c.n2[3] = 1000 * 2048;
        convA<<<dim3(8192, 4), 256>>>(c);
    }
    // 0b) weight transpose+split: src [K,N] -> dst [N,K]
    {
        TArg t = {};
        int i = 0;
        auto add = [&](const float* s, u16* h, u16* l, int K, int N) {
            t.src[i] = s; t.dH[i] = h; t.dL[i] = l; t.K[i] = K; t.N[i] = N; i++;
        };
        add(tWq, wqtH, wqtL, 1024, 1024);
        add(dWq, wqdH, wqdL, 1024, 1024);
        add(tWk, wktH, wktL, 4096, 1024);
        add(tWv, wvtH, wvtL, 4096, 1024);
        add(dWk, wkdH, wkdL, 4096, 1024);
        add(dWv, wvdH, wvdL, 4096, 1024);
        add(tWo, wotH, wotL, 1024, 4096);
        add(dWo, wodH, wodL, 1024, 4096);
        add(gW1, gw1H, gw1L, 2048, 1024);
        convB<<<dim3(128, 128, 9), dim3(32, 8)>>>(t);
    }

    // 1) Q projections, merged (z=2): (4096,1024) x (1024,1024)
    {
        GArg a = {};
        a.AH[0] = trH; a.AL[0] = trL; a.BH[0] = wqtH; a.BL[0] = wqtL;
        a.bias[0] = tbq; a.C[0] = Qt;
        a.AH[1] = deH; a.AL[1] = deL; a.BH[1] = wqdH; a.BL[1] = wqdL;
        a.bias[1] = dbq; a.C[1] = Qd;
        a.M = 4096; a.N = 1024; a.K = 1024; a.Ksplit = 0;
        tgemm<0, false><<<dim3(8, 32, 2), 256, SMEM_DYN>>>(a);
    }
    // 2) K/V projections, merged (z=4): (1000,4096) x (4096,1024)
    {
        GArg a = {};
        a.AH[0] = pTH; a.AL[0] = pTL; a.BH[0] = wktH; a.BL[0] = wktL; a.bias[0] = tbk; a.C[0] = Kt;
        a.AH[1] = pTH; a.AL[1] = pTL; a.BH[1] = wvtH; a.BL[1] = wvtL; a.bias[1] = tbv; a.C[1] = Vt;
        a.AH[2] = pDH; a.AL[2] = pDL; a.BH[2] = wkdH; a.BL[2] = wkdL; a.bias[2] = dbk; a.C[2] = Kd;
        a.AH[3] = pDH; a.AL[3] = pDL; a.BH[3] = wvdH; a.BL[3] = wvdL; a.bias[3] = dbv; a.C[3] = Vd;
        a.M = 1000; a.N = 1024; a.K = 4096; a.Ksplit = 0;
        tgemm<0, false><<<dim3(8, 8, 4), 256, SMEM_DYN>>>(a);
    }
    // 3) attention (writes bf16 hi/lo context planes)
    {
        FArg fa = {};
        fa.Q[0] = Qt; fa.Kb[0] = Kt; fa.Vb[0] = Vt; fa.OH[0] = (u32*)ctH; fa.OL[0] = (u32*)ctL;
        fa.Q[1] = Qd; fa.Kb[1] = Kd; fa.Vb[1] = Vd; fa.OH[1] = (u32*)cdH; fa.OL[1] = (u32*)cdL;
        flash_attn<<<dim3(8, 16, 16), 64>>>(fa, 1000);
    }
    // 4) gate MLP layer 1: H = relu([trend|detail] @ gW1 + gb1), dual-K
    {
        GArg a = {};
        a.AH[0] = trH; a.AL[0] = trL; a.A2H[0] = deH; a.A2L[0] = deL;
        a.BH[0] = gw1H; a.BL[0] = gw1L; a.bias[0] = gb1; a.C[0] = H;
        a.M = 4096; a.N = 1024; a.K = 2048; a.Ksplit = 1024;
        tgemm<1, true><<<dim3(8, 32, 1), 256, SMEM_DYN>>>(a);
    }
    // 5) gate
    gate_kernel<<<512, 256>>>(H, gW2, gb2, G);

    // 6) output projections + fused blend
    {
        GArg a = {};
        a.AH[0] = cdH; a.AL[0] = cdL; a.BH[0] = wodH; a.BL[0] = wodL;
        a.bias[0] = dbo; a.C[0] = out;
        a.M = 4096; a.N = 4096; a.K = 1024; a.Ksplit = 0;
        tgemm<0, false><<<dim3(32, 32, 1), 256, SMEM_DYN>>>(a);
    }
    {
        GArg a = {};
        a.AH[0] = ctH; a.AL[0] = ctL; a.BH[0] = wotH; a.BL[0] = wotL;
        a.bias[0] = tbo; a.C[0] = out; a.gate = G;
        a.M = 4096; a.N = 4096; a.K = 1024; a.Ksplit = 0;
        tgemm<3, false><<<dim3(32, 32, 1), 256, SMEM_DYN>>>(a);
    }

    (void)in_sizes; (void)n_in; (void)out_size;
}

// round 8
// speedup vs baseline: 1.6187x; 1.0099x over previous
#include <cuda_runtime.h>
#include <cuda_bf16.h>
#include <cstdint>

typedef unsigned long long u64;
typedef unsigned int u32;
typedef unsigned short u16;

// ---------------- packed fp32x2 helpers (attention kernel) ----------------
__device__ __forceinline__ u64 pack2(float x, float y) {
    u64 r; asm("mov.b64 %0, {%1, %2};" : "=l"(r) : "f"(x), "f"(y)); return r;
}
__device__ __forceinline__ float2 unpack2(u64 v) {
    float2 r; asm("mov.b64 {%0, %1}, %2;" : "=f"(r.x), "=f"(r.y) : "l"(v)); return r;
}
__device__ __forceinline__ void fma2(u64& d, u64 a, u64 b) {
    asm("fma.rn.f32x2 %0, %1, %2, %0;" : "+l"(d) : "l"(a), "l"(b));
}
__device__ __forceinline__ u64 mul2(u64 a, u64 b) {
    u64 d; asm("mul.rn.f32x2 %0, %1, %2;" : "=l"(d) : "l"(a), "l"(b)); return d;
}

// ---------------- bf16 helpers ----------------
__device__ __forceinline__ u32 packbf(float v0, float v1) {
    u32 r; asm("cvt.rn.bf16x2.f32 %0, %1, %2;" : "=r"(r) : "f"(v1), "f"(v0));
    return r;
}
__device__ __forceinline__ float bf_lo_f(u32 w) { return __uint_as_float(w << 16); }
__device__ __forceinline__ float bf_hi_f(u32 w) { return __uint_as_float(w & 0xffff0000u); }

// m16n8k16 bf16 MMA, row.col, fp32 accumulate
__device__ __forceinline__ void mma16(float* c, u32 a0, u32 a1, u32 a2, u32 a3,
                                      u32 b0, u32 b1) {
    asm volatile("mma.sync.aligned.m16n8k16.row.col.f32.bf16.bf16.f32 "
                 "{%0,%1,%2,%3}, {%4,%5,%6,%7}, {%8,%9}, {%0,%1,%2,%3};"
                 : "+f"(c[0]), "+f"(c[1]), "+f"(c[2]), "+f"(c[3])
                 : "r"(a0), "r"(a1), "r"(a2), "r"(a3), "r"(b0), "r"(b1));
}

// ---------------- cp.async / ldmatrix ----------------
__device__ __forceinline__ u32 smem_u32(const void* p) {
    u32 a; asm("{ .reg .u64 t; cvta.to.shared.u64 t, %1; cvt.u32.u64 %0, t; }"
                : "=r"(a) : "l"(p));
    return a;
}
__device__ __forceinline__ void cpasync16(u32 dst, const void* src, int srcsize) {
    asm volatile("cp.async.cg.shared.global [%0], [%1], 16, %2;"
                 :: "r"(dst), "l"(src), "r"(srcsize) : "memory");
}
__device__ __forceinline__ void cpcommit() {
    asm volatile("cp.async.commit_group;" ::: "memory");
}
template<int N> __device__ __forceinline__ void cpwait() {
    asm volatile("cp.async.wait_group %0;" :: "n"(N) : "memory");
}
__device__ __forceinline__ void ldsm4(u32& r0, u32& r1, u32& r2, u32& r3, u32 addr) {
    asm volatile("ldmatrix.sync.aligned.m8n8.x4.shared.b16 {%0,%1,%2,%3}, [%4];"
                 : "=r"(r0), "=r"(r1), "=r"(r2), "=r"(r3) : "r"(addr));
}

// ---------------- scratch (device globals: allocation-free) ----------------
__device__ float g_Qt[4096 * 1024];
__device__ float g_Qd[4096 * 1024];
__device__ float g_Kt[1024 * 1024];
__device__ float g_Vt[1024 * 1024];
__device__ float g_Kd[1024 * 1024];
__device__ float g_Vd[1024 * 1024];
__device__ float g_H [4096 * 1024];
__device__ float g_gate[4096];
__device__ u16 g_trH[4096 * 1024], g_trL[4096 * 1024];
__device__ u16 g_deH[4096 * 1024], g_deL[4096 * 1024];
__device__ u16 g_pTH[1000 * 4096], g_pTL[1000 * 4096];
__device__ u16 g_pDH[1000 * 4096], g_pDL[1000 * 4096];
__device__ u16 g_ctH[4096 * 1024], g_ctL[4096 * 1024];
__device__ u16 g_cdH[4096 * 1024], g_cdL[4096 * 1024];
__device__ u16 g_wqtH[1024 * 1024], g_wqtL[1024 * 1024];
__device__ u16 g_wqdH[1024 * 1024], g_wqdL[1024 * 1024];
__device__ u16 g_wktH[1024 * 4096], g_wktL[1024 * 4096];
__device__ u16 g_wvtH[1024 * 4096], g_wvtL[1024 * 4096];
__device__ u16 g_wkdH[1024 * 4096], g_wkdL[1024 * 4096];
__device__ u16 g_wvdH[1024 * 4096], g_wvdL[1024 * 4096];
__device__ u16 g_wotH[4096 * 1024], g_wotL[4096 * 1024];
__device__ u16 g_wodH[4096 * 1024], g_wodL[4096 * 1024];
__device__ u16 g_gw1H[1024 * 2048], g_gw1L[1024 * 2048];

// ---------------- pre-pass: elementwise fp32 -> bf16 hi/lo ----------------
struct CArg { const float* src[4]; u32* dH[4]; u32* dL[4]; int n2[4]; };
__global__ __launch_bounds__(256)
void convA(CArg c)
{
    int z = blockIdx.y;
    int i = blockIdx.x * 256 + threadIdx.x;
    if (i >= c.n2[z]) return;
    float2 v = ((const float2*)c.src[z])[i];
    u32 hw = packbf(v.x, v.y);
    float l0 = v.x - bf_lo_f(hw);
    float l1 = v.y - bf_hi_f(hw);
    c.dH[z][i] = hw;
    c.dL[z][i] = packbf(l0, l1);
}

// ---------------- pre-pass: transpose [K,N] fp32 -> [N,K] bf16 hi/lo -------
struct TArg { const float* src[9]; u16* dH[9]; u16* dL[9]; int K[9]; int N[9]; };
__global__ __launch_bounds__(256)
void convB(TArg t)
{
    __shared__ float tile[32][33];
    int z = blockIdx.z;
    int K = t.K[z], N = t.N[z];
    int k0 = blockIdx.x * 32, n0 = blockIdx.y * 32;
    if (k0 >= K || n0 >= N) return;
    const float* src = t.src[z];
    #pragma unroll
    for (int r = 0; r < 4; r++)
        tile[threadIdx.y + r * 8][threadIdx.x] =
            src[(size_t)(k0 + threadIdx.y + r * 8) * N + n0 + threadIdx.x];
    __syncthreads();
    u16* dH = t.dH[z]; u16* dL = t.dL[z];
    #pragma unroll
    for (int r = 0; r < 4; r++) {
        int n = n0 + threadIdx.y + r * 8;
        int k = k0 + threadIdx.x;
        float v = tile[threadIdx.x][threadIdx.y + r * 8];
        __nv_bfloat16 h = __float2bfloat16(v);
        float hf = __bfloat162float(h);
        __nv_bfloat16 l = __float2bfloat16(v - hf);
        dH[(size_t)n * K + k] = *(u16*)&h;
        dL[(size_t)n * K + k] = *(u16*)&l;
    }
}

// ---------------- GEMM argument block ----------------
struct GArg {
    const u16* AH[4]; const u16* AL[4];
    const u16* A2H[4]; const u16* A2L[4];
    const u16* BH[4]; const u16* BL[4];     // [N,K] layout
    const float* bias[4];
    float* C[4];
    const float* gate;
    int M, N, K, Ksplit;
};

// ---------------- HMMA 3xBF16 GEMM: 3-stage cp.async ring + ldmatrix --------
// D += Ah*Bh + Ah*Bl + Al*Bh, fp32 accum. 128x128 CTA tile, k-stage 16.
// Per stage: 4 planes (Ah, Al, Bh, Bl), 128 rows x 48B. One barrier/stage.
static constexpr int ROWB   = 48;
static constexpr int PLANEB = 128 * ROWB;        // 6144
static constexpr int STAGEB = 4 * PLANEB;        // 24576
static constexpr int NSTG   = 3;
static constexpr int SMEM_DYN = NSTG * STAGEB;   // 73728

template<int EPI, bool DUAL>
__global__ __launch_bounds__(256, 2)
void tgemm(GArg g)
{
    extern __shared__ __align__(16) char smem[];
    const u32 sb = smem_u32(smem);

    const int tid  = threadIdx.x;
    const int wid  = tid >> 5;
    const int lane = tid & 31;
    const int gq   = lane >> 2;
    const int tq   = lane & 3;
    const int wr   = (wid & 1) * 64;
    const int wc   = (wid >> 1) * 32;

    const int z = blockIdx.z;
    const u16* __restrict__ AH  = g.AH[z];
    const u16* __restrict__ AL  = g.AL[z];
    const u16* __restrict__ A2H = g.A2H[z];
    const u16* __restrict__ A2L = g.A2L[z];
    const u16* __restrict__ BH  = g.BH[z];
    const u16* __restrict__ BL  = g.BL[z];
    const float* __restrict__ bias = g.bias[z];
    float* __restrict__ C          = g.C[z];
    const int M = g.M, N = g.N, K = g.K, Ksp = g.Ksplit;
    const int lda = DUAL ? Ksp : K;
    const int row0 = blockIdx.y * 128;
    const int col0 = blockIdx.x * 128;

    float acc[4][4][4];
    #pragma unroll
    for (int i = 0; i < 4; i++)
        #pragma unroll
        for (int j = 0; j < 4; j++)
            #pragma unroll
            for (int q = 0; q < 4; q++) acc[i][j][q] = 0.f;

    const int cRow  = tid >> 1;
    const int cHalf = tid & 1;

    auto issue = [&](int s, int buf) {
        const int k0 = s * 16;
        const u32 dbase = sb + buf * STAGEB + cRow * ROWB + cHalf * 16;
        {
            int kk = k0 + cHalf * 8;
            const u16* bh = AH; const u16* bl = AL;
            if (DUAL && kk >= Ksp) { bh = A2H; bl = A2L; kk -= Ksp; }
            int gr = row0 + cRow;
            int ok = (gr < M) ? 16 : 0;
            int grc = (gr < M) ? gr : (M - 1);
            cpasync16(dbase,          bh + (size_t)grc * lda + kk, ok);
            cpasync16(dbase + PLANEB, bl + (size_t)grc * lda + kk, ok);
        }
        {
            int kk = k0 + cHalf * 8;
            size_t off = (size_t)(col0 + cRow) * K + kk;
            cpasync16(dbase + 2 * PLANEB, BH + off, 16);
            cpasync16(dbase + 3 * PLANEB, BL + off, 16);
        }
    };

    const int lr = lane & 7;
    const int lb = (lane >> 3) & 1;
    const int lh = lane >> 4;
    const u32 aoff = (u32)((wr + lb * 8 + lr) * ROWB + lh * 16);
    const u32 boff = (u32)((wc + lh * 8 + lr) * ROWB + lb * 16) + 2 * PLANEB;

    auto compute = [&](int buf) {
        const u32 base = sb + buf * STAGEB;
        u32 ah[4][4], bh[4][2], bl[4][2];
        #pragma unroll
        for (int mi = 0; mi < 4; mi++)
            ldsm4(ah[mi][0], ah[mi][1], ah[mi][2], ah[mi][3],
                  base + aoff + mi * (16 * ROWB));
        #pragma unroll
        for (int nj = 0; nj < 2; nj++)
            ldsm4(bh[2 * nj][0], bh[2 * nj][1], bh[2 * nj + 1][0], bh[2 * nj + 1][1],
                  base + boff + nj * (16 * ROWB));
        #pragma unroll
        for (int mi = 0; mi < 4; mi++)
            #pragma unroll
            for (int ni = 0; ni < 4; ni++)
                mma16(acc[mi][ni], ah[mi][0], ah[mi][1], ah[mi][2], ah[mi][3],
                      bh[ni][0], bh[ni][1]);
        #pragma unroll
        for (int nj = 0; nj < 2; nj++)
            ldsm4(bl[2 * nj][0], bl[2 * nj][1], bl[2 * nj + 1][0], bl[2 * nj + 1][1],
                  base + boff + PLANEB + nj * (16 * ROWB));
        #pragma unroll
        for (int mi = 0; mi < 4; mi++)
            #pragma unroll
            for (int ni = 0; ni < 4; ni++)
                mma16(acc[mi][ni], ah[mi][0], ah[mi][1], ah[mi][2], ah[mi][3],
                      bl[ni][0], bl[ni][1]);
        #pragma unroll
        for (int mi = 0; mi < 4; mi++)          // reuse ah regs for Al
            ldsm4(ah[mi][0], ah[mi][1], ah[mi][2], ah[mi][3],
                  base + aoff + PLANEB + mi * (16 * ROWB));
        #pragma unroll
        for (int mi = 0; mi < 4; mi++)
            #pragma unroll
            for (int ni = 0; ni < 4; ni++)
                mma16(acc[mi][ni], ah[mi][0], ah[mi][1], ah[mi][2], ah[mi][3],
                      bh[ni][0], bh[ni][1]);
    };

    const int nst = K / 16;
    // prologue: NSTG-1 stages in flight
    #pragma unroll
    for (int p = 0; p < NSTG - 1; p++) {
        if (p < nst) issue(p, p);
        cpcommit();
    }

    int buf = 0;
    for (int s = 0; s < nst; s++) {
        cpwait<NSTG - 2>();
        __syncthreads();          // stage s resident for all; stage s-1 fully consumed
        int nxt = s + NSTG - 1;
        if (nxt < nst) issue(nxt, (nxt >= NSTG) ? (nxt - NSTG >= 0 ? (nxt % NSTG) : nxt) : nxt);
        cpcommit();               // unconditional: keeps wait-count arithmetic uniform
        compute(buf);
        buf = (buf + 1 == NSTG) ? 0 : buf + 1;
    }

    // epilogue
    #pragma unroll
    for (int mi = 0; mi < 4; mi++) {
        #pragma unroll
        for (int rr = 0; rr < 2; rr++) {
            int r = row0 + wr + mi * 16 + gq + rr * 8;
            if (r >= M) continue;
            float gg = (EPI == 3) ? g.gate[r] : 0.f;
            #pragma unroll
            for (int ni = 0; ni < 4; ni++) {
                int c = col0 + wc + ni * 8 + tq * 2;
                size_t idx = (size_t)r * N + c;
                float s0 = acc[mi][ni][rr * 2 + 0] + bias[c];
                float s1 = acc[mi][ni][rr * 2 + 1] + bias[c + 1];
                float2 o;
                if (EPI == 0) {
                    o = make_float2(s0, s1);
                } else if (EPI == 1) {
                    o = make_float2(fmaxf(s0, 0.f), fmaxf(s1, 0.f));
                } else {
                    float2 old = *(const float2*)(C + idx);
                    o = make_float2(old.x + gg * (s0 - old.x),
                                    old.y + gg * (s1 - old.y));
                }
                *(float2*)(C + idx) = o;
            }
        }
    }
}

// ---------------- flash attention -> bf16 hi/lo output planes ----------------
struct FArg {
    const float* Q[2];
    const float* Kb[2];
    const float* Vb[2];
    u32* OH[2];
    u32* OL[2];
};

__global__ __launch_bounds__(64)
void flash_attn(FArg f, int S)
{
    __shared__ __align__(16) u64 Ks[64 * 32];
    __shared__ __align__(16) u64 Vs[64 * 32];
    __shared__ float Ss[64 * 64];
    const int tid = threadIdx.x;
    const int h   = blockIdx.y;
    const int sel = blockIdx.z >> 3;
    const int b   = blockIdx.z & 7;
    const int row = b * 512 + blockIdx.x * 64 + tid;

    const float* __restrict__ Q  = f.Q[sel];
    const float* __restrict__ Kb = f.Kb[sel];
    const float* __restrict__ Vb = f.Vb[sel];

    const u64* qp = (const u64*)(Q + (size_t)row * 1024 + h * 64);
    u64 q2[32];
    #pragma unroll
    for (int i = 0; i < 32; i++) q2[i] = qp[i];

    u64 acc2[32] = {};
    float m = -1e30f, lsum = 0.f;
    const float scale = 0.125f;

    for (int s0 = 0; s0 < S; s0 += 64) {
        int jmax = S - s0; if (jmax > 64) jmax = 64;
        #pragma unroll
        for (int i = 0; i < 32; i++) {
            int idx = i * 64 + tid;
            int j = idx >> 5, e2 = idx & 31;
            int srow = s0 + j;
            u64 kv = 0, vv = 0;
            if (srow < S) {
                kv = ((const u64*)(Kb + (size_t)srow * 1024 + h * 64))[e2];
                vv = ((const u64*)(Vb + (size_t)srow * 1024 + h * 64))[e2];
            }
            Ks[idx] = kv; Vs[idx] = vv;
        }
        __syncthreads();

        float tmax = -1e30f;
        for (int j = 0; j < 64; j++) {
            float s;
            if (j < jmax) {
                u64 s2 = 0;
                const ulonglong2* kp = (const ulonglong2*)&Ks[j * 32];
                #pragma unroll
                for (int e = 0; e < 16; e++) {
                    ulonglong2 kv = kp[e];
                    fma2(s2, q2[e * 2],     kv.x);
                    fma2(s2, q2[e * 2 + 1], kv.y);
                }
                float2 sf = unpack2(s2);
                s = (sf.x + sf.y) * scale;
            } else {
                s = -1e30f;
            }
            tmax = fmaxf(tmax, s);
            Ss[j * 64 + tid] = s;
        }

        float mnew  = fmaxf(m, tmax);
        float alpha = __expf(m - mnew);
        lsum *= alpha;
        u64 a2 = pack2(alpha, alpha);
        #pragma unroll
        for (int e = 0; e < 32; e++) acc2[e] = mul2(acc2[e], a2);

        for (int j = 0; j < 64; j++) {
            float p = __expf(Ss[j * 64 + tid] - mnew);
            lsum += p;
            u64 p2 = pack2(p, p);
            const ulonglong2* vp = (const ulonglong2*)&Vs[j * 32];
            #pragma unroll
            for (int e = 0; e < 16; e++) {
                ulonglong2 vv = vp[e];
                fma2(acc2[e * 2],     p2, vv.x);
                fma2(acc2[e * 2 + 1], p2, vv.y);
            }
        }
        m = mnew;
        __syncthreads();
    }

    float inv = 1.f / lsum;
    u32* OH = f.OH[sel];
    u32* OL = f.OL[sel];
    size_t obase = (size_t)row * 512 + h * 32;
    #pragma unroll
    for (int e = 0; e < 32; e++) {
        float2 v = unpack2(acc2[e]);
        v.x *= inv; v.y *= inv;
        u32 hw = packbf(v.x, v.y);
        float l0 = v.x - bf_lo_f(hw);
        float l1 = v.y - bf_hi_f(hw);
        OH[obase + e] = hw;
        OL[obase + e] = packbf(l0, l1);
    }
}

// ---------------- gate: G[r] = sigmoid(H[r,:] . W2 + b2), one warp per row ----
__global__ __launch_bounds__(256)
void gate_kernel(const float* __restrict__ H, const float* __restrict__ W2,
                 const float* __restrict__ b2, float* __restrict__ G)
{
    int w = (blockIdx.x * blockDim.x + threadIdx.x) >> 5;
    int lane = threadIdx.x & 31;
    const float* hp = H + (size_t)w * 1024;
    float s = 0.f;
    #pragma unroll
    for (int i = 0; i < 32; i++) s += hp[lane + i * 32] * W2[lane + i * 32];
    #pragma unroll
    for (int o = 16; o; o >>= 1) s += __shfl_xor_sync(0xffffffffu, s, o);
    if (lane == 0) G[w] = 1.f / (1.f + __expf(-(s + b2[0])));
}

// ---------------- launch ----------------
extern "C" void kernel_launch(void* const* d_in, const int* in_sizes, int n_in,
                              void* d_out, int out_size)
{
    const float* trend  = (const float*)d_in[0];
    const float* detail = (const float*)d_in[1];
    const float* protoT = (const float*)d_in[2];
    const float* protoD = (const float*)d_in[3];
    const float* tWq = (const float*)d_in[4];  const float* tbq = (const float*)d_in[5];
    const float* tWk = (const float*)d_in[6];  const float* tbk = (const float*)d_in[7];
    const float* tWv = (const float*)d_in[8];  const float* tbv = (const float*)d_in[9];
    const float* tWo = (const float*)d_in[10]; const float* tbo = (const float*)d_in[11];
    const float* dWq = (const float*)d_in[12]; const float* dbq = (const float*)d_in[13];
    const float* dWk = (const float*)d_in[14]; const float* dbk = (const float*)d_in[15];
    const float* dWv = (const float*)d_in[16]; const float* dbv = (const float*)d_in[17];
    const float* dWo = (const float*)d_in[18]; const float* dbo = (const float*)d_in[19];
    const float* gW1 = (const float*)d_in[20]; const float* gb1 = (const float*)d_in[21];
    const float* gW2 = (const float*)d_in[22]; const float* gb2 = (const float*)d_in[23];
    float* out = (float*)d_out;

    #define SYM(T, v, s) T* v; cudaGetSymbolAddress((void**)&v, s)
    SYM(float, Qt, g_Qt);   SYM(float, Qd, g_Qd);
    SYM(float, Kt, g_Kt);   SYM(float, Vt, g_Vt);
    SYM(float, Kd, g_Kd);   SYM(float, Vd, g_Vd);
    SYM(float, H,  g_H);    SYM(float, G,  g_gate);
    SYM(u16, trH, g_trH);   SYM(u16, trL, g_trL);
    SYM(u16, deH, g_deH);   SYM(u16, deL, g_deL);
    SYM(u16, pTH, g_pTH);   SYM(u16, pTL, g_pTL);
    SYM(u16, pDH, g_pDH);   SYM(u16, pDL, g_pDL);
    SYM(u16, ctH, g_ctH);   SYM(u16, ctL, g_ctL);
    SYM(u16, cdH, g_cdH);   SYM(u16, cdL, g_cdL);
    SYM(u16, wqtH, g_wqtH); SYM(u16, wqtL, g_wqtL);
    SYM(u16, wqdH, g_wqdH); SYM(u16, wqdL, g_wqdL);
    SYM(u16, wktH, g_wktH); SYM(u16, wktL, g_wktL);
    SYM(u16, wvtH, g_wvtH); SYM(u16, wvtL, g_wvtL);
    SYM(u16, wkdH, g_wkdH); SYM(u16, wkdL, g_wkdL);
    SYM(u16, wvdH, g_wvdH); SYM(u16, wvdL, g_wvdL);
    SYM(u16, wotH, g_wotH); SYM(u16, wotL, g_wotL);
    SYM(u16, wodH, g_wodH); SYM(u16, wodL, g_wodL);
    SYM(u16, gw1H, g_gw1H); SYM(u16, gw1L, g_gw1L);
    #undef SYM

    cudaFuncSetAttribute(tgemm<0, false>, cudaFuncAttributeMaxDynamicSharedMemorySize, SMEM_DYN);
    cudaFuncSetAttribute(tgemm<1, true >, cudaFuncAttributeMaxDynamicSharedMemorySize, SMEM_DYN);
    cudaFuncSetAttribute(tgemm<3, false>, cudaFuncAttributeMaxDynamicSharedMemorySize, SMEM_DYN);

    // 0a) A-side conversions
    {
        CArg c = {};
        c.src[0] = trend;  c.dH[0] = (u32*)trH; c.dL[0] = (u32*)trL; c.n2[0] = 4096 * 512;
        c.src[1] = detail; c.dH[1] = (u32*)deH; c.dL[1] = (u32*)deL; c.n2[1] = 4096 * 512;
        c.src[2] = protoT; c.dH[2] = (u32*)pTH; c.dL[2] = (u32*)pTL; c.n2[2] = 1000 * 2048;
        c.src[3] = protoD; c.dH[3] = (u32*)pDH; c.dL[3] = (u32*)pDL; c.n2[3] = 1000 * 2048;
        convA<<<dim3(8192, 4), 256>>>(c);
    }
    // 0b) weight transpose+split
    {
        TArg t = {};
        int i = 0;
        auto add = [&](const float* s, u16* h, u16* l, int K, int N) {
            t.src[i] = s; t.dH[i] = h; t.dL[i] = l; t.K[i] = K; t.N[i] = N; i++;
        };
        add(tWq, wqtH, wqtL, 1024, 1024);
        add(dWq, wqdH, wqdL, 1024, 1024);
        add(tWk, wktH, wktL, 4096, 1024);
        add(tWv, wvtH, wvtL, 4096, 1024);
        add(dWk, wkdH, wkdL, 4096, 1024);
        add(dWv, wvdH, wvdL, 4096, 1024);
        add(tWo, wotH, wotL, 1024, 4096);
        add(dWo, wodH, wodL, 1024, 4096);
        add(gW1, gw1H, gw1L, 2048, 1024);
        convB<<<dim3(128, 128, 9), dim3(32, 8)>>>(t);
    }

    // 1) Q projections, merged (z=2)
    {
        GArg a = {};
        a.AH[0] = trH; a.AL[0] = trL; a.BH[0] = wqtH; a.BL[0] = wqtL;
        a.bias[0] = tbq; a.C[0] = Qt;
        a.AH[1] = deH; a.AL[1] = deL; a.BH[1] = wqdH; a.BL[1] = wqdL;
        a.bias[1] = dbq; a.C[1] = Qd;
        a.M = 4096; a.N = 1024; a.K = 1024; a.Ksplit = 0;
        tgemm<0, false><<<dim3(8, 32, 2), 256, SMEM_DYN>>>(a);
    }
    // 2) K/V projections, merged (z=4)
    {
        GArg a = {};
        a.AH[0] = pTH; a.AL[0] = pTL; a.BH[0] = wktH; a.BL[0] = wktL; a.bias[0] = tbk; a.C[0] = Kt;
        a.AH[1] = pTH; a.AL[1] = pTL; a.BH[1] = wvtH; a.BL[1] = wvtL; a.bias[1] = tbv; a.C[1] = Vt;
        a.AH[2] = pDH; a.AL[2] = pDL; a.BH[2] = wkdH; a.BL[2] = wkdL; a.bias[2] = dbk; a.C[2] = Kd;
        a.AH[3] = pDH; a.AL[3] = pDL; a.BH[3] = wvdH; a.BL[3] = wvdL; a.bias[3] = dbv; a.C[3] = Vd;
        a.M = 1000; a.N = 1024; a.K = 4096; a.Ksplit = 0;
        tgemm<0, false><<<dim3(8, 8, 4), 256, SMEM_DYN>>>(a);
    }
    // 3) attention (writes bf16 hi/lo context planes)
    {
        FArg fa = {};
        fa.Q[0] = Qt; fa.Kb[0] = Kt; fa.Vb[0] = Vt; fa.OH[0] = (u32*)ctH; fa.OL[0] = (u32*)ctL;
        fa.Q[1] = Qd; fa.Kb[1] = Kd; fa.Vb[1] = Vd; fa.OH[1] = (u32*)cdH; fa.OL[1] = (u32*)cdL;
        flash_attn<<<dim3(8, 16, 16), 64>>>(fa, 1000);
    }
    // 4) gate MLP layer 1: H = relu([trend|detail] @ gW1 + gb1), dual-K
    {
        GArg a = {};
        a.AH[0] = trH; a.AL[0] = trL; a.A2H[0] = deH; a.A2L[0] = deL;
        a.BH[0] = gw1H; a.BL[0] = gw1L; a.bias[0] = gb1; a.C[0] = H;
        a.M = 4096; a.N = 1024; a.K = 2048; a.Ksplit = 1024;
        tgemm<1, true><<<dim3(8, 32, 1), 256, SMEM_DYN>>>(a);
    }
    // 5) gate
    gate_kernel<<<512, 256>>>(H, gW2, gb2, G);

    // 6) output projections + fused blend
    {
        GArg a = {};
        a.AH[0] = cdH; a.AL[0] = cdL; a.BH[0] = wodH; a.BL[0] = wodL;
        a.bias[0] = dbo; a.C[0] = out;
        a.M = 4096; a.N = 4096; a.K = 1024; a.Ksplit = 0;
        tgemm<0, false><<<dim3(32, 32, 1), 256, SMEM_DYN>>>(a);
    }
    {
        GArg a = {};
        a.AH[0] = ctH; a.AL[0] = ctL; a.BH[0] = wotH; a.BL[0] = wotL;
        a.bias[0] = tbo; a.C[0] = out; a.gate = G;
        a.M = 4096; a.N = 4096; a.K = 1024; a.Ksplit = 0;
        tgemm<3, false><<<dim3(32, 32, 1), 256, SMEM_DYN>>>(a);
    }

    (void)in_sizes; (void)n_in; (void)out_size;
}